// round 12
// baseline (speedup 1.0000x reference)
#include <cuda_runtime.h>
#include <cuda_fp16.h>
#include <cstdint>
#include <math.h>

#define NROWS 204800
#define NG    2048
#define NPGC  100
#define MB    1600            // NROWS / 128

// ---- scratch (device globals; allocation forbidden) ----
__device__ __half d_Yh0[NROWS * 256];
__device__ __half d_Yh1[NROWS * 256];
__device__ __half d_Wh0[256 * 256];
__device__ __half d_Wh1[256 * 256];
__device__ __half d_Wmh[256 * 512];
__device__ float d_psum  [2 * MB * 256];
__device__ float d_psumsq[2 * MB * 256];
__device__ float d_psum2  [128 * 256];
__device__ float d_psumsq2[128 * 256];
__device__ float d_bnscale[512];
__device__ float d_bnshift[512];
__device__ __half d_bns_h[512];
__device__ __half d_bnh_h[512];
__device__ float d_wu[16 * 256];        // rows 0..7: ws_h ; rows 8..15: u_h
__device__ float d_cconst[1];
__device__ float d_st[NROWS * 16];      // per row: [scores(8) | t(8)]

// ---- helpers ----
__device__ __forceinline__ unsigned hpack(float a, float b) {
    __half2 h = __floats2half2_rn(a, b);
    return *reinterpret_cast<unsigned*>(&h);
}
__device__ __forceinline__ void mma_f16(float c[4],
    unsigned a0, unsigned a1, unsigned a2, unsigned a3, unsigned b0, unsigned b1)
{
    asm volatile(
        "mma.sync.aligned.m16n8k16.row.col.f32.f16.f16.f32 "
        "{%0,%1,%2,%3},{%4,%5,%6,%7},{%8,%9},{%0,%1,%2,%3};"
        : "+f"(c[0]), "+f"(c[1]), "+f"(c[2]), "+f"(c[3])
        : "r"(a0), "r"(a1), "r"(a2), "r"(a3), "r"(b0), "r"(b1));
}
__device__ __forceinline__ void ldsm4(unsigned& r0, unsigned& r1, unsigned& r2, unsigned& r3,
                                      uint32_t addr)
{
    asm volatile("ldmatrix.sync.aligned.m8n8.x4.shared.b16 {%0,%1,%2,%3}, [%4];"
        : "=r"(r0), "=r"(r1), "=r"(r2), "=r"(r3) : "r"(addr));
}
__device__ __forceinline__ void cp16(uint32_t dst, const void* src) {
    asm volatile("cp.async.cg.shared.global [%0], [%1], 16;" :: "r"(dst), "l"(src) : "memory");
}
__device__ __forceinline__ void cp_commit() {
    asm volatile("cp.async.commit_group;" ::: "memory");
}
template<int N> __device__ __forceinline__ void cp_wait() {
    asm volatile("cp.async.wait_group %0;" :: "n"(N) : "memory");
}

// ---- gemm1 staging: Ah (128 rows x 80B) + Bh (128 rows x 80B), BK=32 ----
constexpr int G1_BH   = 10240;            // Bh offset (Ah at 0)
constexpr int G1_STG  = 20480;            // per stage
constexpr int SMEM1g  = 3 * G1_STG;       // 61440

// ---- gemm2 (merged N=256) staging: BK=64 ----
constexpr int G2_B    = 16384;                    // B offset (A = 128x128B)
constexpr int G2_STG  = 16384 + 32768;            // 49152 per stage
constexpr int SMEM2g  = 3 * G2_STG + 2048;        // 149504

// ============================================================================
// convert weights to half
// ============================================================================
__global__ void convert_w(const float* __restrict__ W0, const float* __restrict__ W1,
                          const float* __restrict__ Wm)
{
    int t = blockIdx.x * 256 + threadIdx.x;    // 0..65535
    const float* src; __half* dst; int k;
    if (t < 16384)      { src = W0; dst = d_Wh0; k = t; }
    else if (t < 32768) { src = W1; dst = d_Wh1; k = t - 16384; }
    else                { src = Wm; dst = d_Wmh; k = t - 32768; }
    const float4 v = reinterpret_cast<const float4*>(src)[k];
    uint2 w; w.x = hpack(v.x, v.y); w.y = hpack(v.z, v.w);
    reinterpret_cast<uint2*>(dst)[k] = w;
}

// ============================================================================
// Kernel 1: fold weights -> ws_h, u_h, cconst
// ============================================================================
__global__ void prep_kernel(const float* __restrict__ ipW, const float* __restrict__ ipb,
                            const float* __restrict__ opW, const float* __restrict__ opb,
                            const float* __restrict__ rW,  const float* __restrict__ rb)
{
    __shared__ float q[256];
    __shared__ float r2[256];
    __shared__ float red[256];
    const int tid = threadIdx.x;

    float s = 0.f;
    for (int k = 0; k < 256; k += 4) {
        float4 v = *reinterpret_cast<const float4*>(&ipW[tid * 256 + k]);
        s += v.x + v.y + v.z + v.w;
    }
    q[tid] = (s + ipb[tid]) * 0.17677669529663687f;

    float s2 = 0.f;
    for (int c = 0; c < 256; c++) s2 += rW[c] * opW[c * 256 + tid];
    r2[tid] = s2;
    __syncthreads();

    const int c = tid;
    for (int h = 0; h < 8; h++) {
        float a = 0.f, u = 0.f;
        #pragma unroll 8
        for (int d = 0; d < 32; d++) {
            a += q [h * 32 + d] * ipW[(256 + h * 32 + d) * 256 + c];
            u += r2[h * 32 + d] * ipW[(512 + h * 32 + d) * 256 + c];
        }
        d_wu[h * 256 + c]       = a;
        d_wu[(8 + h) * 256 + c] = u;
    }

    red[tid] = ipb[512 + tid] * r2[tid] + rW[tid] * opb[tid];
    __syncthreads();
    for (int off = 128; off; off >>= 1) {
        if (tid < off) red[tid] += red[tid + off];
        __syncthreads();
    }
    if (tid == 0) d_cconst[0] = red[0] + rb[0];
}

// ============================================================================
// Kernel 2: fp16 MMA GEMM  Y = X @ W^T + b  + column stats
// grid (2 nblk, MB, 2 mat), 256 threads, BK=32, 8 chunks
// A path: LDG fp32 -> regs -> cvt -> STS half (no fp32 smem staging)
// B path: cp.async 3-stage
// ============================================================================
__global__ __launch_bounds__(256, 2)
void gemm1(const float* __restrict__ X0, const float* __restrict__ X1,
           const float* __restrict__ B0, const float* __restrict__ B1)
{
    extern __shared__ char sm[];
    const uint32_t sa = (uint32_t)__cvta_generic_to_shared(sm);

    const int nblk = blockIdx.x;
    const int rb   = blockIdx.y;
    const int mat  = blockIdx.z;
    const float*  __restrict__ Xf = mat ? X1 : X0;
    const __half* __restrict__ Wh = mat ? d_Wh1 : d_Wh0;
    const float*  __restrict__ bias = (mat ? B1 : B0) + nblk * 128;

    const int tid = threadIdx.x, lane = tid & 31, wid = tid >> 5;
    const int wm = wid >> 2, wn = wid & 3;
    const int g = lane >> 2, tq = lane & 3;
    const int row0 = rb * 128;

    const __half* __restrict__ Brow0 = Wh + nblk * 128 * 256;

    const uint32_t aOff = (uint32_t)((wm * 64 + (lane & 15)) * 80 + ((lane >> 4) * 8) * 2);
    const uint32_t bOff = (uint32_t)(G1_BH + (wn * 32 + (lane & 7) + ((lane >> 4) << 3)) * 80
                                     + (((lane >> 3) & 1) * 8) * 2);

    // A register path: each thread owns (row = tid>>1, 16-float half = tid&1)
    const int arow = tid >> 1;
    const int ac16 = (tid & 1) * 16;
    const float* __restrict__ Xr = Xf + (row0 + arow) * 256 + ac16;

    auto issueB = [&](int s) {
        const uint32_t sb = sa + (s % 3) * G1_STG;
        const int kt = 32 * s;
        #pragma unroll
        for (int jj = 0; jj < 2; jj++) {
            const int p = tid + 256 * jj;
            const int row = p >> 2, c = p & 3;
            cp16(sb + (uint32_t)(G1_BH + row * 80 + c * 16),
                 Brow0 + row * 256 + kt + c * 8);
        }
    };

    float acc[4][4][4];
    #pragma unroll
    for (int mi = 0; mi < 4; mi++)
        #pragma unroll
        for (int ni = 0; ni < 4; ni++)
            #pragma unroll
            for (int e = 0; e < 4; e++) acc[mi][ni][e] = 0.f;

    float4 a4[4];
    #pragma unroll
    for (int j = 0; j < 4; j++) a4[j] = *reinterpret_cast<const float4*>(Xr + 4 * j);
    issueB(0); cp_commit();
    issueB(1); cp_commit();

    #pragma unroll 1
    for (int i = 0; i < 8; i++) {
        if (i < 7) cp_wait<1>(); else cp_wait<0>();
        __syncthreads();

        // STS A(i): convert regs -> half, write RSTR=80 Ah region
        {
            char* stgc = sm + (i % 3) * G1_STG;
            uint4 h0, h1;
            h0.x = hpack(a4[0].x, a4[0].y); h0.y = hpack(a4[0].z, a4[0].w);
            h0.z = hpack(a4[1].x, a4[1].y); h0.w = hpack(a4[1].z, a4[1].w);
            h1.x = hpack(a4[2].x, a4[2].y); h1.y = hpack(a4[2].z, a4[2].w);
            h1.z = hpack(a4[3].x, a4[3].y); h1.w = hpack(a4[3].z, a4[3].w);
            char* dst = stgc + arow * 80 + (tid & 1) * 32;
            *reinterpret_cast<uint4*>(dst)      = h0;
            *reinterpret_cast<uint4*>(dst + 16) = h1;
        }
        __syncthreads();

        if (i < 7) {
            const int ktn = 32 * (i + 1);
            #pragma unroll
            for (int j = 0; j < 4; j++)
                a4[j] = *reinterpret_cast<const float4*>(Xr + ktn + 4 * j);
        }
        if (i + 2 < 8) { issueB(i + 2); cp_commit(); }

        const uint32_t stg = sa + (i % 3) * G1_STG;
        #pragma unroll
        for (int kc = 0; kc < 32; kc += 16) {
            unsigned af[4][4], bf[4][2];
            #pragma unroll
            for (int mi = 0; mi < 4; mi++)
                ldsm4(af[mi][0], af[mi][1], af[mi][2], af[mi][3],
                      stg + aOff + mi * 16 * 80 + kc * 2);
            ldsm4(bf[0][0], bf[0][1], bf[1][0], bf[1][1], stg + bOff + kc * 2);
            ldsm4(bf[2][0], bf[2][1], bf[3][0], bf[3][1], stg + bOff + 16 * 80 + kc * 2);
            #pragma unroll
            for (int mi = 0; mi < 4; mi++)
                #pragma unroll
                for (int ni = 0; ni < 4; ni++)
                    mma_f16(acc[mi][ni], af[mi][0], af[mi][1], af[mi][2], af[mi][3],
                            bf[ni][0], bf[ni][1]);
        }
    }

    // ---- epilogue: bias, write Y (half), column stats ----
    float2 bb[4];
    #pragma unroll
    for (int ni = 0; ni < 4; ni++)
        bb[ni] = *reinterpret_cast<const float2*>(&bias[wn * 32 + ni * 8 + tq * 2]);
    #pragma unroll
    for (int mi = 0; mi < 4; mi++)
        #pragma unroll
        for (int ni = 0; ni < 4; ni++) {
            acc[mi][ni][0] += bb[ni].x; acc[mi][ni][1] += bb[ni].y;
            acc[mi][ni][2] += bb[ni].x; acc[mi][ni][3] += bb[ni].y;
        }

    __half* __restrict__ Y = mat ? d_Yh1 : d_Yh0;
    const int colbase = nblk * 128 + wn * 32;
    #pragma unroll
    for (int mi = 0; mi < 4; mi++) {
        const int R0 = row0 + wm * 64 + mi * 16 + g;
        #pragma unroll
        for (int ni = 0; ni < 4; ni++) {
            const int gc = colbase + ni * 8 + tq * 2;
            *reinterpret_cast<unsigned*>(&Y[R0 * 256 + gc])       = hpack(acc[mi][ni][0], acc[mi][ni][1]);
            *reinterpret_cast<unsigned*>(&Y[(R0 + 8) * 256 + gc]) = hpack(acc[mi][ni][2], acc[mi][ni][3]);
        }
    }

    __syncthreads();
    float* ssum = reinterpret_cast<float*>(sm);       // [2][128]
    float* ssq  = ssum + 256;
    #pragma unroll
    for (int ni = 0; ni < 4; ni++) {
        float s0 = 0.f, s1 = 0.f, q0 = 0.f, q1 = 0.f;
        #pragma unroll
        for (int mi = 0; mi < 4; mi++) {
            const float v0 = acc[mi][ni][0], v1 = acc[mi][ni][1];
            const float v2 = acc[mi][ni][2], v3 = acc[mi][ni][3];
            s0 += v0 + v2; s1 += v1 + v3;
            q0 += v0 * v0 + v2 * v2; q1 += v1 * v1 + v3 * v3;
        }
        #pragma unroll
        for (int off = 4; off < 32; off <<= 1) {
            s0 += __shfl_xor_sync(0xffffffffu, s0, off);
            s1 += __shfl_xor_sync(0xffffffffu, s1, off);
            q0 += __shfl_xor_sync(0xffffffffu, q0, off);
            q1 += __shfl_xor_sync(0xffffffffu, q1, off);
        }
        if (lane < 4) {
            const int lcol = wn * 32 + ni * 8 + tq * 2;
            ssum[wm * 128 + lcol] = s0;  ssum[wm * 128 + lcol + 1] = s1;
            ssq [wm * 128 + lcol] = q0;  ssq [wm * 128 + lcol + 1] = q1;
        }
    }
    __syncthreads();
    if (tid < 128) {
        const int gidx = (mat * MB + rb) * 256 + nblk * 128 + tid;
        d_psum  [gidx] = ssum[tid] + ssum[128 + tid];
        d_psumsq[gidx] = ssq [tid] + ssq [128 + tid];
    }
}

// ============================================================================
// Kernels 3/4: deterministic stat reduction -> BN scale/shift
// ============================================================================
__global__ void stats_partial()   // grid 128
{
    const int mat = blockIdx.x >> 6;
    const int sl  = blockIdx.x & 63;
    const int col = threadIdx.x;
    float s = 0.f, q = 0.f;
    const int rb0 = sl * (MB / 64);     // 25 rowblocks each
    for (int rbi = rb0; rbi < rb0 + (MB / 64); rbi++) {
        s += d_psum  [(mat * MB + rbi) * 256 + col];
        q += d_psumsq[(mat * MB + rbi) * 256 + col];
    }
    d_psum2  [blockIdx.x * 256 + col] = s;
    d_psumsq2[blockIdx.x * 256 + col] = q;
}

__global__ void stats_final(const float* __restrict__ g0, const float* __restrict__ be0,
                            const float* __restrict__ g1, const float* __restrict__ be1)
{
    const int mat = blockIdx.x;
    const int col = threadIdx.x;
    float s = 0.f, q = 0.f;
    #pragma unroll
    for (int sl = 0; sl < 64; sl++) {
        s += d_psum2  [(mat * 64 + sl) * 256 + col];
        q += d_psumsq2[(mat * 64 + sl) * 256 + col];
    }
    const float inv  = 1.0f / (float)NROWS;
    const float mean = s * inv;
    const float var  = fmaxf(q * inv - mean * mean, 0.f);
    const float* gg = mat ? g1 : g0;
    const float* bb = mat ? be1 : be0;
    const float sc = gg[col] * rsqrtf(var + 1e-5f);
    const float sh = bb[col] - mean * sc;
    d_bnscale[mat * 256 + col] = sc;
    d_bnshift[mat * 256 + col] = sh;
    d_bns_h[mat * 256 + col] = __float2half(sc);
    d_bnh_h[mat * 256 + col] = __float2half(sh);
}

// ============================================================================
// Kernel 5: merged fp16 MMA merge GEMM: tile 128x256, 512 threads, BK=64
// grid (MB), 16 warps (wm 0..1 x wn 0..7), 3-stage cp.async, in-place BN+ReLU
// ============================================================================
__global__ __launch_bounds__(512, 1)
void gemm2(const float* __restrict__ bm)
{
    extern __shared__ char sm[];
    const uint32_t sa = (uint32_t)__cvta_generic_to_shared(sm);
    __half2* bns2 = reinterpret_cast<__half2*>(sm + 3 * G2_STG);        // 256 half2
    __half2* bnh2 = reinterpret_cast<__half2*>(sm + 3 * G2_STG + 1024); // 256 half2

    const int tid = threadIdx.x, lane = tid & 31, wid = tid >> 5;
    const int wm = wid >> 3, wn = wid & 7;
    const int g = lane >> 2, tq = lane & 3;
    const int row0 = blockIdx.x * 128;

    {
        const unsigned* s_src = reinterpret_cast<const unsigned*>(d_bns_h);
        const unsigned* h_src = reinterpret_cast<const unsigned*>(d_bnh_h);
        if (tid < 256) {
            reinterpret_cast<unsigned*>(bns2)[tid] = s_src[tid];
            reinterpret_cast<unsigned*>(bnh2)[tid] = h_src[tid];
        }
    }

    const int xr   = (lane & 7) << 4;
    const int al16 = (lane >> 4) * 16;
    const int bl16 = ((lane >> 3) & 1) * 16;
    const uint32_t aRow = (uint32_t)((wm * 64 + (lane & 15)) * 128);
    const uint32_t bRow = (uint32_t)(G2_B + (wn * 32 + (lane & 7) + ((lane >> 4) << 3)) * 128);

    const int pcb = (tid & 7) * 16;
    const int pch = (tid & 7) * 8;

    auto issue = [&](int s) {
        const uint32_t sb = sa + (s % 3) * G2_STG;
        const int kt = 64 * s;
        const __half* __restrict__ Ys = (kt < 256) ? d_Yh0 : d_Yh1;
        const int ko = kt & 255;
        #pragma unroll
        for (int j = 0; j < 2; j++) {
            const int row = (tid + 512 * j) >> 3;
            const uint32_t d = sb + (uint32_t)(row * 128 + (pcb ^ ((row & 7) << 4)));
            cp16(d, Ys + (row0 + row) * 256 + ko + pch);
        }
        #pragma unroll
        for (int j = 0; j < 4; j++) {
            const int row = (tid + 512 * j) >> 3;
            const uint32_t d = sb + (uint32_t)(G2_B + row * 128 + (pcb ^ ((row & 7) << 4)));
            cp16(d, d_Wmh + row * 512 + kt + pch);
        }
    };

    float acc[4][4][4];
    #pragma unroll
    for (int mi = 0; mi < 4; mi++)
        #pragma unroll
        for (int ni = 0; ni < 4; ni++)
            #pragma unroll
            for (int e = 0; e < 4; e++) acc[mi][ni][e] = 0.f;

    issue(0); cp_commit();
    issue(1); cp_commit();

    const __half2 z2 = __float2half2_rn(0.f);

    #pragma unroll 1
    for (int i = 0; i < 8; i++) {
        if (i < 7) cp_wait<1>(); else cp_wait<0>();
        __syncthreads();
        if (i + 2 < 8) { issue(i + 2); cp_commit(); }

        char* stgc = sm + (i % 3) * G2_STG;
        const int kt = 64 * i;
        #pragma unroll
        for (int j = 0; j < 2; j++) {
            const int w = tid + 512 * j;
            const int row = w >> 3, c = w & 7;
            __half2* ap = reinterpret_cast<__half2*>(stgc + row * 128 + ((c * 16) ^ ((row & 7) << 4)));
            const int si = (kt >> 1) + c * 4;
            const __half2 s0 = bns2[si], s1 = bns2[si + 1], s2 = bns2[si + 2], s3 = bns2[si + 3];
            const __half2 h0 = bnh2[si], h1 = bnh2[si + 1], h2 = bnh2[si + 2], h3 = bnh2[si + 3];
            __half2 v0 = ap[0], v1 = ap[1], v2 = ap[2], v3 = ap[3];
            v0 = __hmax2(__hfma2(v0, s0, h0), z2);
            v1 = __hmax2(__hfma2(v1, s1, h1), z2);
            v2 = __hmax2(__hfma2(v2, s2, h2), z2);
            v3 = __hmax2(__hfma2(v3, s3, h3), z2);
            ap[0] = v0; ap[1] = v1; ap[2] = v2; ap[3] = v3;
        }
        __syncthreads();

        const uint32_t stg = sa + (i % 3) * G2_STG;
        #pragma unroll
        for (int kc2 = 0; kc2 < 128; kc2 += 32) {
            const int ac = (kc2 + al16) ^ xr;
            const int bc = (kc2 + bl16) ^ xr;
            unsigned af[4][4], bf[4][2];
            #pragma unroll
            for (int mi = 0; mi < 4; mi++)
                ldsm4(af[mi][0], af[mi][1], af[mi][2], af[mi][3],
                      stg + aRow + mi * 2048 + ac);
            ldsm4(bf[0][0], bf[0][1], bf[1][0], bf[1][1], stg + bRow + bc);
            ldsm4(bf[2][0], bf[2][1], bf[3][0], bf[3][1], stg + bRow + 2048 + bc);
            #pragma unroll
            for (int mi = 0; mi < 4; mi++)
                #pragma unroll
                for (int ni = 0; ni < 4; ni++)
                    mma_f16(acc[mi][ni], af[mi][0], af[mi][1], af[mi][2], af[mi][3],
                            bf[ni][0], bf[ni][1]);
        }
    }

    // ---- epilogue: bias, 16-way wu dot, combine 8 warp partials, write d_st ----
    #pragma unroll
    for (int ni = 0; ni < 4; ni++) {
        const float2 bb = *reinterpret_cast<const float2*>(&bm[wn * 32 + ni * 8 + tq * 2]);
        #pragma unroll
        for (int mi = 0; mi < 4; mi++) {
            acc[mi][ni][0] += bb.x; acc[mi][ni][1] += bb.y;
            acc[mi][ni][2] += bb.x; acc[mi][ni][3] += bb.y;
        }
    }

    __syncthreads();
    float* wuS = reinterpret_cast<float*>(sm);           // [16][256] = 16 KB
    float* stS = reinterpret_cast<float*>(sm) + 4096;    // [8 wn][128 rows][16 h] = 64 KB
    #pragma unroll
    for (int j = 0; j < 8; j++) wuS[tid + 512 * j] = d_wu[tid + 512 * j];
    __syncthreads();

    #pragma unroll
    for (int h = 0; h < 16; h++) {
        float2 wv[4];
        #pragma unroll
        for (int ni = 0; ni < 4; ni++)
            wv[ni] = *reinterpret_cast<const float2*>(&wuS[h * 256 + wn * 32 + ni * 8 + tq * 2]);
        #pragma unroll
        for (int mi = 0; mi < 4; mi++) {
            float p0 = 0.f, p1 = 0.f;
            #pragma unroll
            for (int ni = 0; ni < 4; ni++) {
                p0 += acc[mi][ni][0] * wv[ni].x + acc[mi][ni][1] * wv[ni].y;
                p1 += acc[mi][ni][2] * wv[ni].x + acc[mi][ni][3] * wv[ni].y;
            }
            p0 += __shfl_xor_sync(0xffffffffu, p0, 1);
            p0 += __shfl_xor_sync(0xffffffffu, p0, 2);
            p1 += __shfl_xor_sync(0xffffffffu, p1, 1);
            p1 += __shfl_xor_sync(0xffffffffu, p1, 2);
            if (tq == 0) {
                const int rl = wm * 64 + mi * 16 + g;
                stS[wn * 2048 + rl * 16 + h]       = p0;
                stS[wn * 2048 + (rl + 8) * 16 + h] = p1;
            }
        }
    }
    __syncthreads();
    {
        const int rowl = tid >> 2, hh = (tid & 3) * 4;   // 512 threads x 4 values
        float v[4];
        #pragma unroll
        for (int j = 0; j < 4; j++) {
            float s = 0.f;
            #pragma unroll
            for (int w = 0; w < 8; w++) s += stS[w * 2048 + rowl * 16 + hh + j];
            v[j] = s;
        }
        *reinterpret_cast<float4*>(&d_st[(row0 + rowl) * 16 + hh]) =
            make_float4(v[0], v[1], v[2], v[3]);
    }
}

// ============================================================================
// Kernel 6: per-group softmax-weighted mean + tanh readout
// ============================================================================
__global__ void groups_kernel(float* __restrict__ out)
{
    __shared__ float sb[NPGC * 16];
    __shared__ float hv[8];
    const int g = blockIdx.x;
    const int tid = threadIdx.x;
    const float* __restrict__ b0 = &d_st[g * (NPGC * 16)];
    for (int i = tid; i < NPGC * 16; i += 256) sb[i] = b0[i];
    __syncthreads();

    const int h    = tid >> 5;
    const int lane = tid & 31;

    float mx = -1e30f;
    for (int r = lane; r < NPGC; r += 32) mx = fmaxf(mx, sb[r * 16 + h]);
    #pragma unroll
    for (int off = 16; off; off >>= 1) mx = fmaxf(mx, __shfl_xor_sync(0xffffffffu, mx, off));

    float num = 0.f, den = 0.f;
    for (int r = lane; r < NPGC; r += 32) {
        const float e = expf(sb[r * 16 + h] - mx);
        num = fmaf(e, sb[r * 16 + 8 + h], num);
        den += e;
    }
    #pragma unroll
    for (int off = 16; off; off >>= 1) {
        num += __shfl_xor_sync(0xffffffffu, num, off);
        den += __shfl_xor_sync(0xffffffffu, den, off);
    }
    if (lane == 0) hv[h] = num / den;
    __syncthreads();

    if (tid == 0) {
        float s = d_cconst[0];
        #pragma unroll
        for (int i = 0; i < 8; i++) s += hv[i];
        out[g] = tanhf(s);
    }
}

// ============================================================================
extern "C" void kernel_launch(void* const* d_in, const int* in_sizes, int n_in,
                              void* d_out, int out_size)
{
    const float* x0   = (const float*)d_in[0];
    const float* x1   = (const float*)d_in[1];
    const float* p0W  = (const float*)d_in[3];
    const float* p0b  = (const float*)d_in[4];
    const float* p0g  = (const float*)d_in[5];
    const float* p0be = (const float*)d_in[6];
    const float* p1W  = (const float*)d_in[7];
    const float* p1b  = (const float*)d_in[8];
    const float* p1g  = (const float*)d_in[9];
    const float* p1be = (const float*)d_in[10];
    const float* mW   = (const float*)d_in[11];
    const float* mb   = (const float*)d_in[12];
    const float* ipW  = (const float*)d_in[13];
    const float* ipb  = (const float*)d_in[14];
    const float* opW  = (const float*)d_in[15];
    const float* opb  = (const float*)d_in[16];
    const float* rW   = (const float*)d_in[17];
    const float* rb   = (const float*)d_in[18];
    float* out = (float*)d_out;

    cudaFuncSetAttribute(gemm1, cudaFuncAttributeMaxDynamicSharedMemorySize, SMEM1g);
    cudaFuncSetAttribute(gemm2, cudaFuncAttributeMaxDynamicSharedMemorySize, SMEM2g);

    prep_kernel<<<1, 256>>>(ipW, ipb, opW, opb, rW, rb);
    convert_w<<<256, 256>>>(p0W, p1W, mW);
    gemm1<<<dim3(2, MB, 2), 256, SMEM1g>>>(x0, x1, p0b, p1b);
    stats_partial<<<128, 256>>>();
    stats_final<<<2, 256>>>(p0g, p0be, p1g, p1be);
    gemm2<<<MB, 512, SMEM2g>>>(mb);
    groups_kernel<<<NG, 256>>>(out);
}

// round 13
// speedup vs baseline: 1.0748x; 1.0748x over previous
#include <cuda_runtime.h>
#include <cuda_fp16.h>
#include <cstdint>
#include <math.h>

#define NROWS 204800
#define NG    2048
#define NPGC  100
#define MB    1600            // NROWS / 128

// ---- scratch (device globals; allocation forbidden) ----
__device__ __half d_Yh0[NROWS * 256];
__device__ __half d_Yh1[NROWS * 256];
__device__ __half d_Wh0[256 * 256];
__device__ __half d_Wh1[256 * 256];
__device__ __half d_Wmh[256 * 512];
__device__ float d_psum  [2 * MB * 256];
__device__ float d_psumsq[2 * MB * 256];
__device__ float d_psum2  [128 * 256];
__device__ float d_psumsq2[128 * 256];
__device__ float d_bnscale[512];
__device__ float d_bnshift[512];
__device__ __half d_bns_h[512];
__device__ __half d_bnh_h[512];
__device__ float d_wu[16 * 256];        // rows 0..7: ws_h ; rows 8..15: u_h
__device__ float d_cconst[1];
__device__ float d_st[NROWS * 16];      // per row: [scores(8) | t(8)]

// ---- helpers ----
__device__ __forceinline__ unsigned hpack(float a, float b) {
    __half2 h = __floats2half2_rn(a, b);
    return *reinterpret_cast<unsigned*>(&h);
}
__device__ __forceinline__ void mma_f16(float c[4],
    unsigned a0, unsigned a1, unsigned a2, unsigned a3, unsigned b0, unsigned b1)
{
    asm volatile(
        "mma.sync.aligned.m16n8k16.row.col.f32.f16.f16.f32 "
        "{%0,%1,%2,%3},{%4,%5,%6,%7},{%8,%9},{%0,%1,%2,%3};"
        : "+f"(c[0]), "+f"(c[1]), "+f"(c[2]), "+f"(c[3])
        : "r"(a0), "r"(a1), "r"(a2), "r"(a3), "r"(b0), "r"(b1));
}
__device__ __forceinline__ void ldsm4(unsigned& r0, unsigned& r1, unsigned& r2, unsigned& r3,
                                      uint32_t addr)
{
    asm volatile("ldmatrix.sync.aligned.m8n8.x4.shared.b16 {%0,%1,%2,%3}, [%4];"
        : "=r"(r0), "=r"(r1), "=r"(r2), "=r"(r3) : "r"(addr));
}
__device__ __forceinline__ void cp16(uint32_t dst, const void* src) {
    asm volatile("cp.async.cg.shared.global [%0], [%1], 16;" :: "r"(dst), "l"(src) : "memory");
}
__device__ __forceinline__ void cp_commit() {
    asm volatile("cp.async.commit_group;" ::: "memory");
}
template<int N> __device__ __forceinline__ void cp_wait() {
    asm volatile("cp.async.wait_group %0;" :: "n"(N) : "memory");
}

// ---- gemm1 staging rings: Ah x2 (80B rows), B x4 (80B rows), Af32 x3 (128B rows) ----
constexpr int G1_AH   = 0;                 // 2 * 10240
constexpr int G1_B    = 20480;             // 4 * 10240
constexpr int G1_AF   = 61440;             // 3 * 16384
constexpr int SMEM1g  = 61440 + 49152;     // 110592

// ---- gemm2 (merged N=256) staging: BK=64 ----
constexpr int G2_B    = 16384;                    // B offset (A = 128x128B)
constexpr int G2_STG  = 16384 + 32768;            // 49152 per stage
constexpr int SMEM2g  = 3 * G2_STG + 2048;        // 149504

// ============================================================================
// convert weights to half
// ============================================================================
__global__ void convert_w(const float* __restrict__ W0, const float* __restrict__ W1,
                          const float* __restrict__ Wm)
{
    int t = blockIdx.x * 256 + threadIdx.x;    // 0..65535
    const float* src; __half* dst; int k;
    if (t < 16384)      { src = W0; dst = d_Wh0; k = t; }
    else if (t < 32768) { src = W1; dst = d_Wh1; k = t - 16384; }
    else                { src = Wm; dst = d_Wmh; k = t - 32768; }
    const float4 v = reinterpret_cast<const float4*>(src)[k];
    uint2 w; w.x = hpack(v.x, v.y); w.y = hpack(v.z, v.w);
    reinterpret_cast<uint2*>(dst)[k] = w;
}

// ============================================================================
// Kernel 1: fold weights -> ws_h, u_h, cconst
// ============================================================================
__global__ void prep_kernel(const float* __restrict__ ipW, const float* __restrict__ ipb,
                            const float* __restrict__ opW, const float* __restrict__ opb,
                            const float* __restrict__ rW,  const float* __restrict__ rb)
{
    __shared__ float q[256];
    __shared__ float r2[256];
    __shared__ float red[256];
    const int tid = threadIdx.x;

    float s = 0.f;
    for (int k = 0; k < 256; k += 4) {
        float4 v = *reinterpret_cast<const float4*>(&ipW[tid * 256 + k]);
        s += v.x + v.y + v.z + v.w;
    }
    q[tid] = (s + ipb[tid]) * 0.17677669529663687f;

    float s2 = 0.f;
    for (int c = 0; c < 256; c++) s2 += rW[c] * opW[c * 256 + tid];
    r2[tid] = s2;
    __syncthreads();

    const int c = tid;
    for (int h = 0; h < 8; h++) {
        float a = 0.f, u = 0.f;
        #pragma unroll 8
        for (int d = 0; d < 32; d++) {
            a += q [h * 32 + d] * ipW[(256 + h * 32 + d) * 256 + c];
            u += r2[h * 32 + d] * ipW[(512 + h * 32 + d) * 256 + c];
        }
        d_wu[h * 256 + c]       = a;
        d_wu[(8 + h) * 256 + c] = u;
    }

    red[tid] = ipb[512 + tid] * r2[tid] + rW[tid] * opb[tid];
    __syncthreads();
    for (int off = 128; off; off >>= 1) {
        if (tid < off) red[tid] += red[tid + off];
        __syncthreads();
    }
    if (tid == 0) d_cconst[0] = red[0] + rb[0];
}

// ============================================================================
// Kernel 2: fused fp32->half + fp16 MMA GEMM  Y = X @ W^T + b  + column stats
// grid (2 nblk, MB, 2 mat), 256 threads, BK=32, 8 chunks
// Software-pipelined convert: 1 sync per chunk
// ============================================================================
__global__ __launch_bounds__(256, 2)
void gemm1(const float* __restrict__ X0, const float* __restrict__ X1,
           const float* __restrict__ B0, const float* __restrict__ B1)
{
    extern __shared__ char sm[];
    const uint32_t sa = (uint32_t)__cvta_generic_to_shared(sm);

    const int nblk = blockIdx.x;
    const int rb   = blockIdx.y;
    const int mat  = blockIdx.z;
    const float*  __restrict__ Xf = mat ? X1 : X0;
    const __half* __restrict__ Wh = mat ? d_Wh1 : d_Wh0;
    const float*  __restrict__ bias = (mat ? B1 : B0) + nblk * 128;

    const int tid = threadIdx.x, lane = tid & 31, wid = tid >> 5;
    const int wm = wid >> 2, wn = wid & 3;
    const int g = lane >> 2, tq = lane & 3;
    const int row0 = rb * 128;

    const __half* __restrict__ Brow0 = Wh + nblk * 128 * 256;

    const uint32_t aOff = (uint32_t)((wm * 64 + (lane & 15)) * 80 + ((lane >> 4) * 8) * 2);
    const uint32_t bOff = (uint32_t)((wn * 32 + (lane & 7) + ((lane >> 4) << 3)) * 80
                                     + (((lane >> 3) & 1) * 8) * 2);

    auto issue = [&](int s) {
        const uint32_t af = sa + G1_AF + (s % 3) * 16384;
        const uint32_t bb = sa + G1_B  + (s & 3) * 10240;
        const int kt = 32 * s;
        // A: 1024 fp32 16B pieces (128 rows x 128B, xor-swizzled) -> 4 per thread
        #pragma unroll
        for (int jj = 0; jj < 4; jj++) {
            const int p = tid + 256 * jj;
            const int row = p >> 3, c = p & 7;
            cp16(af + (uint32_t)(row * 128 + ((c * 16) ^ ((row & 7) << 4))),
                 Xf + (row0 + row) * 256 + kt + c * 4);
        }
        // B: 512 half 16B pieces (128 rows x 64B into RSTR=80) -> 2 per thread
        #pragma unroll
        for (int jj = 0; jj < 2; jj++) {
            const int p = tid + 256 * jj;
            const int row = p >> 2, c = p & 3;
            cp16(bb + (uint32_t)(row * 80 + c * 16),
                 Brow0 + row * 256 + kt + c * 8);
        }
    };

    auto convert = [&](int s) {
        char* af = sm + G1_AF + (s % 3) * 16384;
        char* ah = sm + G1_AH + (s & 1) * 10240;
        #pragma unroll
        for (int jj = 0; jj < 2; jj++) {
            const int w = tid + 256 * jj;
            const int row = w >> 2, c8 = w & 3;
            const int xo = (row & 7) << 4;
            const float4 f0 = *reinterpret_cast<const float4*>(af + row * 128 + ((c8 * 32) ^ xo));
            const float4 f1 = *reinterpret_cast<const float4*>(af + row * 128 + ((c8 * 32 + 16) ^ xo));
            uint4 hv;
            hv.x = hpack(f0.x, f0.y); hv.y = hpack(f0.z, f0.w);
            hv.z = hpack(f1.x, f1.y); hv.w = hpack(f1.z, f1.w);
            *reinterpret_cast<uint4*>(ah + row * 80 + c8 * 16) = hv;
        }
    };

    float acc[4][4][4];
    #pragma unroll
    for (int mi = 0; mi < 4; mi++)
        #pragma unroll
        for (int ni = 0; ni < 4; ni++)
            #pragma unroll
            for (int e = 0; e < 4; e++) acc[mi][ni][e] = 0.f;

    issue(0); cp_commit();
    issue(1); cp_commit();
    issue(2); cp_commit();
    cp_wait<2>();               // group 0 complete
    __syncthreads();
    convert(0);                 // Ah(0) ready after next sync

    #pragma unroll 1
    for (int i = 0; i < 8; i++) {
        if (i < 6) cp_wait<1>(); else cp_wait<0>();   // group (i+1) complete
        __syncthreads();        // orders convert(i) writes + cp arrivals

        if (i + 1 < 8) convert(i + 1);                // Af32(i+1) -> Ah(i+1)
        if (i + 3 < 8) { issue(i + 3); cp_commit(); }

        const uint32_t ah = sa + G1_AH + (i & 1) * 10240;
        const uint32_t bb = sa + G1_B  + (i & 3) * 10240;
        #pragma unroll
        for (int kc = 0; kc < 32; kc += 16) {
            unsigned af[4][4], bf[4][2];
            #pragma unroll
            for (int mi = 0; mi < 4; mi++)
                ldsm4(af[mi][0], af[mi][1], af[mi][2], af[mi][3],
                      ah + aOff + mi * 16 * 80 + kc * 2);
            ldsm4(bf[0][0], bf[0][1], bf[1][0], bf[1][1], bb + bOff + kc * 2);
            ldsm4(bf[2][0], bf[2][1], bf[3][0], bf[3][1], bb + bOff + 16 * 80 + kc * 2);
            #pragma unroll
            for (int mi = 0; mi < 4; mi++)
                #pragma unroll
                for (int ni = 0; ni < 4; ni++)
                    mma_f16(acc[mi][ni], af[mi][0], af[mi][1], af[mi][2], af[mi][3],
                            bf[ni][0], bf[ni][1]);
        }
    }

    // ---- epilogue: bias, write Y (half), column stats ----
    float2 bb2[4];
    #pragma unroll
    for (int ni = 0; ni < 4; ni++)
        bb2[ni] = *reinterpret_cast<const float2*>(&bias[wn * 32 + ni * 8 + tq * 2]);
    #pragma unroll
    for (int mi = 0; mi < 4; mi++)
        #pragma unroll
        for (int ni = 0; ni < 4; ni++) {
            acc[mi][ni][0] += bb2[ni].x; acc[mi][ni][1] += bb2[ni].y;
            acc[mi][ni][2] += bb2[ni].x; acc[mi][ni][3] += bb2[ni].y;
        }

    __half* __restrict__ Y = mat ? d_Yh1 : d_Yh0;
    const int colbase = nblk * 128 + wn * 32;
    #pragma unroll
    for (int mi = 0; mi < 4; mi++) {
        const int R0 = row0 + wm * 64 + mi * 16 + g;
        #pragma unroll
        for (int ni = 0; ni < 4; ni++) {
            const int gc = colbase + ni * 8 + tq * 2;
            *reinterpret_cast<unsigned*>(&Y[R0 * 256 + gc])       = hpack(acc[mi][ni][0], acc[mi][ni][1]);
            *reinterpret_cast<unsigned*>(&Y[(R0 + 8) * 256 + gc]) = hpack(acc[mi][ni][2], acc[mi][ni][3]);
        }
    }

    __syncthreads();
    float* ssum = reinterpret_cast<float*>(sm);       // [2][128]
    float* ssq  = ssum + 256;
    #pragma unroll
    for (int ni = 0; ni < 4; ni++) {
        float s0 = 0.f, s1 = 0.f, q0 = 0.f, q1 = 0.f;
        #pragma unroll
        for (int mi = 0; mi < 4; mi++) {
            const float v0 = acc[mi][ni][0], v1 = acc[mi][ni][1];
            const float v2 = acc[mi][ni][2], v3 = acc[mi][ni][3];
            s0 += v0 + v2; s1 += v1 + v3;
            q0 += v0 * v0 + v2 * v2; q1 += v1 * v1 + v3 * v3;
        }
        #pragma unroll
        for (int off = 4; off < 32; off <<= 1) {
            s0 += __shfl_xor_sync(0xffffffffu, s0, off);
            s1 += __shfl_xor_sync(0xffffffffu, s1, off);
            q0 += __shfl_xor_sync(0xffffffffu, q0, off);
            q1 += __shfl_xor_sync(0xffffffffu, q1, off);
        }
        if (lane < 4) {
            const int lcol = wn * 32 + ni * 8 + tq * 2;
            ssum[wm * 128 + lcol] = s0;  ssum[wm * 128 + lcol + 1] = s1;
            ssq [wm * 128 + lcol] = q0;  ssq [wm * 128 + lcol + 1] = q1;
        }
    }
    __syncthreads();
    if (tid < 128) {
        const int gidx = (mat * MB + rb) * 256 + nblk * 128 + tid;
        d_psum  [gidx] = ssum[tid] + ssum[128 + tid];
        d_psumsq[gidx] = ssq [tid] + ssq [128 + tid];
    }
}

// ============================================================================
// Kernels 3/4: deterministic stat reduction -> BN scale/shift
// ============================================================================
__global__ void stats_partial()   // grid 128
{
    const int mat = blockIdx.x >> 6;
    const int sl  = blockIdx.x & 63;
    const int col = threadIdx.x;
    float s = 0.f, q = 0.f;
    const int rb0 = sl * (MB / 64);     // 25 rowblocks each
    for (int rbi = rb0; rbi < rb0 + (MB / 64); rbi++) {
        s += d_psum  [(mat * MB + rbi) * 256 + col];
        q += d_psumsq[(mat * MB + rbi) * 256 + col];
    }
    d_psum2  [blockIdx.x * 256 + col] = s;
    d_psumsq2[blockIdx.x * 256 + col] = q;
}

__global__ void stats_final(const float* __restrict__ g0, const float* __restrict__ be0,
                            const float* __restrict__ g1, const float* __restrict__ be1)
{
    const int mat = blockIdx.x;
    const int col = threadIdx.x;
    float s = 0.f, q = 0.f;
    #pragma unroll
    for (int sl = 0; sl < 64; sl++) {
        s += d_psum2  [(mat * 64 + sl) * 256 + col];
        q += d_psumsq2[(mat * 64 + sl) * 256 + col];
    }
    const float inv  = 1.0f / (float)NROWS;
    const float mean = s * inv;
    const float var  = fmaxf(q * inv - mean * mean, 0.f);
    const float* gg = mat ? g1 : g0;
    const float* bb = mat ? be1 : be0;
    const float sc = gg[col] * rsqrtf(var + 1e-5f);
    const float sh = bb[col] - mean * sc;
    d_bnscale[mat * 256 + col] = sc;
    d_bnshift[mat * 256 + col] = sh;
    d_bns_h[mat * 256 + col] = __float2half(sc);
    d_bnh_h[mat * 256 + col] = __float2half(sh);
}

// ============================================================================
// Kernel 5: merged fp16 MMA merge GEMM: tile 128x256, 512 threads, BK=64
// grid (MB), 16 warps (wm 0..1 x wn 0..7), 3-stage cp.async, in-place BN+ReLU
// ============================================================================
__global__ __launch_bounds__(512, 1)
void gemm2(const float* __restrict__ bm)
{
    extern __shared__ char sm[];
    const uint32_t sa = (uint32_t)__cvta_generic_to_shared(sm);
    __half2* bns2 = reinterpret_cast<__half2*>(sm + 3 * G2_STG);        // 256 half2
    __half2* bnh2 = reinterpret_cast<__half2*>(sm + 3 * G2_STG + 1024); // 256 half2

    const int tid = threadIdx.x, lane = tid & 31, wid = tid >> 5;
    const int wm = wid >> 3, wn = wid & 7;
    const int g = lane >> 2, tq = lane & 3;
    const int row0 = blockIdx.x * 128;

    {
        const unsigned* s_src = reinterpret_cast<const unsigned*>(d_bns_h);
        const unsigned* h_src = reinterpret_cast<const unsigned*>(d_bnh_h);
        if (tid < 256) {
            reinterpret_cast<unsigned*>(bns2)[tid] = s_src[tid];
            reinterpret_cast<unsigned*>(bnh2)[tid] = h_src[tid];
        }
    }

    const int xr   = (lane & 7) << 4;
    const int al16 = (lane >> 4) * 16;
    const int bl16 = ((lane >> 3) & 1) * 16;
    const uint32_t aRow = (uint32_t)((wm * 64 + (lane & 15)) * 128);
    const uint32_t bRow = (uint32_t)(G2_B + (wn * 32 + (lane & 7) + ((lane >> 4) << 3)) * 128);

    const int pcb = (tid & 7) * 16;
    const int pch = (tid & 7) * 8;

    auto issue = [&](int s) {
        const uint32_t sb = sa + (s % 3) * G2_STG;
        const int kt = 64 * s;
        const __half* __restrict__ Ys = (kt < 256) ? d_Yh0 : d_Yh1;
        const int ko = kt & 255;
        #pragma unroll
        for (int j = 0; j < 2; j++) {
            const int row = (tid + 512 * j) >> 3;
            const uint32_t d = sb + (uint32_t)(row * 128 + (pcb ^ ((row & 7) << 4)));
            cp16(d, Ys + (row0 + row) * 256 + ko + pch);
        }
        #pragma unroll
        for (int j = 0; j < 4; j++) {
            const int row = (tid + 512 * j) >> 3;
            const uint32_t d = sb + (uint32_t)(G2_B + row * 128 + (pcb ^ ((row & 7) << 4)));
            cp16(d, d_Wmh + row * 512 + kt + pch);
        }
    };

    float acc[4][4][4];
    #pragma unroll
    for (int mi = 0; mi < 4; mi++)
        #pragma unroll
        for (int ni = 0; ni < 4; ni++)
            #pragma unroll
            for (int e = 0; e < 4; e++) acc[mi][ni][e] = 0.f;

    issue(0); cp_commit();
    issue(1); cp_commit();

    const __half2 z2 = __float2half2_rn(0.f);

    #pragma unroll 1
    for (int i = 0; i < 8; i++) {
        if (i < 7) cp_wait<1>(); else cp_wait<0>();
        __syncthreads();
        if (i + 2 < 8) { issue(i + 2); cp_commit(); }

        char* stgc = sm + (i % 3) * G2_STG;
        const int kt = 64 * i;
        #pragma unroll
        for (int j = 0; j < 2; j++) {
            const int w = tid + 512 * j;
            const int row = w >> 3, c = w & 7;
            __half2* ap = reinterpret_cast<__half2*>(stgc + row * 128 + ((c * 16) ^ ((row & 7) << 4)));
            const int si = (kt >> 1) + c * 4;
            const __half2 s0 = bns2[si], s1 = bns2[si + 1], s2 = bns2[si + 2], s3 = bns2[si + 3];
            const __half2 h0 = bnh2[si], h1 = bnh2[si + 1], h2 = bnh2[si + 2], h3 = bnh2[si + 3];
            __half2 v0 = ap[0], v1 = ap[1], v2 = ap[2], v3 = ap[3];
            v0 = __hmax2(__hfma2(v0, s0, h0), z2);
            v1 = __hmax2(__hfma2(v1, s1, h1), z2);
            v2 = __hmax2(__hfma2(v2, s2, h2), z2);
            v3 = __hmax2(__hfma2(v3, s3, h3), z2);
            ap[0] = v0; ap[1] = v1; ap[2] = v2; ap[3] = v3;
        }
        __syncthreads();

        const uint32_t stg = sa + (i % 3) * G2_STG;
        #pragma unroll
        for (int kc2 = 0; kc2 < 128; kc2 += 32) {
            const int ac = (kc2 + al16) ^ xr;
            const int bc = (kc2 + bl16) ^ xr;
            unsigned af[4][4], bf[4][2];
            #pragma unroll
            for (int mi = 0; mi < 4; mi++)
                ldsm4(af[mi][0], af[mi][1], af[mi][2], af[mi][3],
                      stg + aRow + mi * 2048 + ac);
            ldsm4(bf[0][0], bf[0][1], bf[1][0], bf[1][1], stg + bRow + bc);
            ldsm4(bf[2][0], bf[2][1], bf[3][0], bf[3][1], stg + bRow + 2048 + bc);
            #pragma unroll
            for (int mi = 0; mi < 4; mi++)
                #pragma unroll
                for (int ni = 0; ni < 4; ni++)
                    mma_f16(acc[mi][ni], af[mi][0], af[mi][1], af[mi][2], af[mi][3],
                            bf[ni][0], bf[ni][1]);
        }
    }

    // ---- epilogue: bias, 16-way wu dot, combine 8 warp partials, write d_st ----
    #pragma unroll
    for (int ni = 0; ni < 4; ni++) {
        const float2 bb = *reinterpret_cast<const float2*>(&bm[wn * 32 + ni * 8 + tq * 2]);
        #pragma unroll
        for (int mi = 0; mi < 4; mi++) {
            acc[mi][ni][0] += bb.x; acc[mi][ni][1] += bb.y;
            acc[mi][ni][2] += bb.x; acc[mi][ni][3] += bb.y;
        }
    }

    __syncthreads();
    float* wuS = reinterpret_cast<float*>(sm);           // [16][256] = 16 KB
    float* stS = reinterpret_cast<float*>(sm) + 4096;    // [8 wn][128 rows][16 h] = 64 KB
    #pragma unroll
    for (int j = 0; j < 8; j++) wuS[tid + 512 * j] = d_wu[tid + 512 * j];
    __syncthreads();

    #pragma unroll
    for (int h = 0; h < 16; h++) {
        float2 wv[4];
        #pragma unroll
        for (int ni = 0; ni < 4; ni++)
            wv[ni] = *reinterpret_cast<const float2*>(&wuS[h * 256 + wn * 32 + ni * 8 + tq * 2]);
        #pragma unroll
        for (int mi = 0; mi < 4; mi++) {
            float p0 = 0.f, p1 = 0.f;
            #pragma unroll
            for (int ni = 0; ni < 4; ni++) {
                p0 += acc[mi][ni][0] * wv[ni].x + acc[mi][ni][1] * wv[ni].y;
                p1 += acc[mi][ni][2] * wv[ni].x + acc[mi][ni][3] * wv[ni].y;
            }
            p0 += __shfl_xor_sync(0xffffffffu, p0, 1);
            p0 += __shfl_xor_sync(0xffffffffu, p0, 2);
            p1 += __shfl_xor_sync(0xffffffffu, p1, 1);
            p1 += __shfl_xor_sync(0xffffffffu, p1, 2);
            if (tq == 0) {
                const int rl = wm * 64 + mi * 16 + g;
                stS[wn * 2048 + rl * 16 + h]       = p0;
                stS[wn * 2048 + (rl + 8) * 16 + h] = p1;
            }
        }
    }
    __syncthreads();
    {
        const int rowl = tid >> 2, hh = (tid & 3) * 4;   // 512 threads x 4 values
        float v[4];
        #pragma unroll
        for (int j = 0; j < 4; j++) {
            float s = 0.f;
            #pragma unroll
            for (int w = 0; w < 8; w++) s += stS[w * 2048 + rowl * 16 + hh + j];
            v[j] = s;
        }
        *reinterpret_cast<float4*>(&d_st[(row0 + rowl) * 16 + hh]) =
            make_float4(v[0], v[1], v[2], v[3]);
    }
}

// ============================================================================
// Kernel 6: per-group softmax-weighted mean + tanh readout
// ============================================================================
__global__ void groups_kernel(float* __restrict__ out)
{
    __shared__ float sb[NPGC * 16];
    __shared__ float hv[8];
    const int g = blockIdx.x;
    const int tid = threadIdx.x;
    const float* __restrict__ b0 = &d_st[g * (NPGC * 16)];
    for (int i = tid; i < NPGC * 16; i += 256) sb[i] = b0[i];
    __syncthreads();

    const int h    = tid >> 5;
    const int lane = tid & 31;

    float mx = -1e30f;
    for (int r = lane; r < NPGC; r += 32) mx = fmaxf(mx, sb[r * 16 + h]);
    #pragma unroll
    for (int off = 16; off; off >>= 1) mx = fmaxf(mx, __shfl_xor_sync(0xffffffffu, mx, off));

    float num = 0.f, den = 0.f;
    for (int r = lane; r < NPGC; r += 32) {
        const float e = expf(sb[r * 16 + h] - mx);
        num = fmaf(e, sb[r * 16 + 8 + h], num);
        den += e;
    }
    #pragma unroll
    for (int off = 16; off; off >>= 1) {
        num += __shfl_xor_sync(0xffffffffu, num, off);
        den += __shfl_xor_sync(0xffffffffu, den, off);
    }
    if (lane == 0) hv[h] = num / den;
    __syncthreads();

    if (tid == 0) {
        float s = d_cconst[0];
        #pragma unroll
        for (int i = 0; i < 8; i++) s += hv[i];
        out[g] = tanhf(s);
    }
}

// ============================================================================
extern "C" void kernel_launch(void* const* d_in, const int* in_sizes, int n_in,
                              void* d_out, int out_size)
{
    const float* x0   = (const float*)d_in[0];
    const float* x1   = (const float*)d_in[1];
    const float* p0W  = (const float*)d_in[3];
    const float* p0b  = (const float*)d_in[4];
    const float* p0g  = (const float*)d_in[5];
    const float* p0be = (const float*)d_in[6];
    const float* p1W  = (const float*)d_in[7];
    const float* p1b  = (const float*)d_in[8];
    const float* p1g  = (const float*)d_in[9];
    const float* p1be = (const float*)d_in[10];
    const float* mW   = (const float*)d_in[11];
    const float* mb   = (const float*)d_in[12];
    const float* ipW  = (const float*)d_in[13];
    const float* ipb  = (const float*)d_in[14];
    const float* opW  = (const float*)d_in[15];
    const float* opb  = (const float*)d_in[16];
    const float* rW   = (const float*)d_in[17];
    const float* rb   = (const float*)d_in[18];
    float* out = (float*)d_out;

    cudaFuncSetAttribute(gemm1, cudaFuncAttributeMaxDynamicSharedMemorySize, SMEM1g);
    cudaFuncSetAttribute(gemm2, cudaFuncAttributeMaxDynamicSharedMemorySize, SMEM2g);

    prep_kernel<<<1, 256>>>(ipW, ipb, opW, opb, rW, rb);
    convert_w<<<256, 256>>>(p0W, p1W, mW);
    gemm1<<<dim3(2, MB, 2), 256, SMEM1g>>>(x0, x1, p0b, p1b);
    stats_partial<<<128, 256>>>();
    stats_final<<<2, 256>>>(p0g, p0be, p1g, p1be);
    gemm2<<<MB, 512, SMEM2g>>>(mb);
    groups_kernel<<<NG, 256>>>(out);
}

// round 14
// speedup vs baseline: 1.0968x; 1.0205x over previous
#include <cuda_runtime.h>
#include <cuda_fp16.h>
#include <cstdint>
#include <math.h>

#define NROWS 204800
#define NG    2048
#define NPGC  100
#define MB    1600            // NROWS / 128

// ---- scratch (device globals; allocation forbidden) ----
__device__ __half d_Yh0[NROWS * 256];
__device__ __half d_Yh1[NROWS * 256];
__device__ __half d_Wh0[256 * 256];
__device__ __half d_Wh1[256 * 256];
__device__ __half d_Wmh[256 * 512];
__device__ float d_psum  [2 * MB * 256];
__device__ float d_psumsq[2 * MB * 256];
__device__ float d_psum2  [128 * 256];
__device__ float d_psumsq2[128 * 256];
__device__ float d_bnscale[512];
__device__ float d_bnshift[512];
__device__ __half d_bns_h[512];
__device__ __half d_bnh_h[512];
__device__ float d_wu[16 * 256];        // rows 0..7: ws_h ; rows 8..15: u_h
__device__ float d_cconst[1];
__device__ float d_st[NROWS * 16];      // per row: [scores(8) | t(8)]

// ---- helpers ----
__device__ __forceinline__ unsigned hpack(float a, float b) {
    __half2 h = __floats2half2_rn(a, b);
    return *reinterpret_cast<unsigned*>(&h);
}
__device__ __forceinline__ void mma_f16(float c[4],
    unsigned a0, unsigned a1, unsigned a2, unsigned a3, unsigned b0, unsigned b1)
{
    asm volatile(
        "mma.sync.aligned.m16n8k16.row.col.f32.f16.f16.f32 "
        "{%0,%1,%2,%3},{%4,%5,%6,%7},{%8,%9},{%0,%1,%2,%3};"
        : "+f"(c[0]), "+f"(c[1]), "+f"(c[2]), "+f"(c[3])
        : "r"(a0), "r"(a1), "r"(a2), "r"(a3), "r"(b0), "r"(b1));
}
__device__ __forceinline__ void ldsm4(unsigned& r0, unsigned& r1, unsigned& r2, unsigned& r3,
                                      uint32_t addr)
{
    asm volatile("ldmatrix.sync.aligned.m8n8.x4.shared.b16 {%0,%1,%2,%3}, [%4];"
        : "=r"(r0), "=r"(r1), "=r"(r2), "=r"(r3) : "r"(addr));
}
__device__ __forceinline__ void cp16(uint32_t dst, const void* src) {
    asm volatile("cp.async.cg.shared.global [%0], [%1], 16;" :: "r"(dst), "l"(src) : "memory");
}
__device__ __forceinline__ void cp_commit() {
    asm volatile("cp.async.commit_group;" ::: "memory");
}
template<int N> __device__ __forceinline__ void cp_wait() {
    asm volatile("cp.async.wait_group %0;" :: "n"(N) : "memory");
}

// ---- gemm1 staging rings: Ah x2 (80B rows), B x4 (80B rows), Af32 x3 (128B rows) ----
constexpr int G1_AH   = 0;                 // 2 * 10240
constexpr int G1_B    = 20480;             // 4 * 10240
constexpr int G1_AF   = 61440;             // 3 * 16384
constexpr int SMEM1g  = 61440 + 49152;     // 110592

// ---- gemm2 rings: Araw x3 (16KB), Ah x2 (16KB), B x4 (32KB) + bn consts ----
constexpr int G2_ARAW = 0;                 // 3 * 16384 = 49152
constexpr int G2_AH   = 49152;             // 2 * 16384 = 32768
constexpr int G2_Bb   = 81920;             // 4 * 32768 = 131072
constexpr int G2_BN   = 212992;            // 2048
constexpr int SMEM2g  = 215040;

// ============================================================================
// convert weights to half
// ============================================================================
__global__ void convert_w(const float* __restrict__ W0, const float* __restrict__ W1,
                          const float* __restrict__ Wm)
{
    int t = blockIdx.x * 256 + threadIdx.x;    // 0..65535
    const float* src; __half* dst; int k;
    if (t < 16384)      { src = W0; dst = d_Wh0; k = t; }
    else if (t < 32768) { src = W1; dst = d_Wh1; k = t - 16384; }
    else                { src = Wm; dst = d_Wmh; k = t - 32768; }
    const float4 v = reinterpret_cast<const float4*>(src)[k];
    uint2 w; w.x = hpack(v.x, v.y); w.y = hpack(v.z, v.w);
    reinterpret_cast<uint2*>(dst)[k] = w;
}

// ============================================================================
// Kernel 1: fold weights -> ws_h, u_h, cconst
// ============================================================================
__global__ void prep_kernel(const float* __restrict__ ipW, const float* __restrict__ ipb,
                            const float* __restrict__ opW, const float* __restrict__ opb,
                            const float* __restrict__ rW,  const float* __restrict__ rb)
{
    __shared__ float q[256];
    __shared__ float r2[256];
    __shared__ float red[256];
    const int tid = threadIdx.x;

    float s = 0.f;
    for (int k = 0; k < 256; k += 4) {
        float4 v = *reinterpret_cast<const float4*>(&ipW[tid * 256 + k]);
        s += v.x + v.y + v.z + v.w;
    }
    q[tid] = (s + ipb[tid]) * 0.17677669529663687f;

    float s2 = 0.f;
    for (int c = 0; c < 256; c++) s2 += rW[c] * opW[c * 256 + tid];
    r2[tid] = s2;
    __syncthreads();

    const int c = tid;
    for (int h = 0; h < 8; h++) {
        float a = 0.f, u = 0.f;
        #pragma unroll 8
        for (int d = 0; d < 32; d++) {
            a += q [h * 32 + d] * ipW[(256 + h * 32 + d) * 256 + c];
            u += r2[h * 32 + d] * ipW[(512 + h * 32 + d) * 256 + c];
        }
        d_wu[h * 256 + c]       = a;
        d_wu[(8 + h) * 256 + c] = u;
    }

    red[tid] = ipb[512 + tid] * r2[tid] + rW[tid] * opb[tid];
    __syncthreads();
    for (int off = 128; off; off >>= 1) {
        if (tid < off) red[tid] += red[tid + off];
        __syncthreads();
    }
    if (tid == 0) d_cconst[0] = red[0] + rb[0];
}

// ============================================================================
// Kernel 2: fused fp32->half + fp16 MMA GEMM  Y = X @ W^T + b  + column stats
// grid (2 nblk, MB, 2 mat), 256 threads, BK=32, 8 chunks, pipelined convert
// ============================================================================
__global__ __launch_bounds__(256, 2)
void gemm1(const float* __restrict__ X0, const float* __restrict__ X1,
           const float* __restrict__ B0, const float* __restrict__ B1)
{
    extern __shared__ char sm[];
    const uint32_t sa = (uint32_t)__cvta_generic_to_shared(sm);

    const int nblk = blockIdx.x;
    const int rb   = blockIdx.y;
    const int mat  = blockIdx.z;
    const float*  __restrict__ Xf = mat ? X1 : X0;
    const __half* __restrict__ Wh = mat ? d_Wh1 : d_Wh0;
    const float*  __restrict__ bias = (mat ? B1 : B0) + nblk * 128;

    const int tid = threadIdx.x, lane = tid & 31, wid = tid >> 5;
    const int wm = wid >> 2, wn = wid & 3;
    const int g = lane >> 2, tq = lane & 3;
    const int row0 = rb * 128;

    const __half* __restrict__ Brow0 = Wh + nblk * 128 * 256;

    const uint32_t aOff = (uint32_t)((wm * 64 + (lane & 15)) * 80 + ((lane >> 4) * 8) * 2);
    const uint32_t bOff = (uint32_t)((wn * 32 + (lane & 7) + ((lane >> 4) << 3)) * 80
                                     + (((lane >> 3) & 1) * 8) * 2);

    auto issue = [&](int s) {
        const uint32_t af = sa + G1_AF + (s % 3) * 16384;
        const uint32_t bb = sa + G1_B  + (s & 3) * 10240;
        const int kt = 32 * s;
        #pragma unroll
        for (int jj = 0; jj < 4; jj++) {
            const int p = tid + 256 * jj;
            const int row = p >> 3, c = p & 7;
            cp16(af + (uint32_t)(row * 128 + ((c * 16) ^ ((row & 7) << 4))),
                 Xf + (row0 + row) * 256 + kt + c * 4);
        }
        #pragma unroll
        for (int jj = 0; jj < 2; jj++) {
            const int p = tid + 256 * jj;
            const int row = p >> 2, c = p & 3;
            cp16(bb + (uint32_t)(row * 80 + c * 16),
                 Brow0 + row * 256 + kt + c * 8);
        }
    };

    auto convert = [&](int s) {
        char* af = sm + G1_AF + (s % 3) * 16384;
        char* ah = sm + G1_AH + (s & 1) * 10240;
        #pragma unroll
        for (int jj = 0; jj < 2; jj++) {
            const int w = tid + 256 * jj;
            const int row = w >> 2, c8 = w & 3;
            const int xo = (row & 7) << 4;
            const float4 f0 = *reinterpret_cast<const float4*>(af + row * 128 + ((c8 * 32) ^ xo));
            const float4 f1 = *reinterpret_cast<const float4*>(af + row * 128 + ((c8 * 32 + 16) ^ xo));
            uint4 hv;
            hv.x = hpack(f0.x, f0.y); hv.y = hpack(f0.z, f0.w);
            hv.z = hpack(f1.x, f1.y); hv.w = hpack(f1.z, f1.w);
            *reinterpret_cast<uint4*>(ah + row * 80 + c8 * 16) = hv;
        }
    };

    float acc[4][4][4];
    #pragma unroll
    for (int mi = 0; mi < 4; mi++)
        #pragma unroll
        for (int ni = 0; ni < 4; ni++)
            #pragma unroll
            for (int e = 0; e < 4; e++) acc[mi][ni][e] = 0.f;

    issue(0); cp_commit();
    issue(1); cp_commit();
    issue(2); cp_commit();
    cp_wait<2>();
    __syncthreads();
    convert(0);

    #pragma unroll 1
    for (int i = 0; i < 8; i++) {
        if (i < 6) cp_wait<1>(); else cp_wait<0>();
        __syncthreads();

        if (i + 1 < 8) convert(i + 1);
        if (i + 3 < 8) { issue(i + 3); cp_commit(); }

        const uint32_t ah = sa + G1_AH + (i & 1) * 10240;
        const uint32_t bb = sa + G1_B  + (i & 3) * 10240;
        #pragma unroll
        for (int kc = 0; kc < 32; kc += 16) {
            unsigned af[4][4], bf[4][2];
            #pragma unroll
            for (int mi = 0; mi < 4; mi++)
                ldsm4(af[mi][0], af[mi][1], af[mi][2], af[mi][3],
                      ah + aOff + mi * 16 * 80 + kc * 2);
            ldsm4(bf[0][0], bf[0][1], bf[1][0], bf[1][1], bb + bOff + kc * 2);
            ldsm4(bf[2][0], bf[2][1], bf[3][0], bf[3][1], bb + bOff + 16 * 80 + kc * 2);
            #pragma unroll
            for (int mi = 0; mi < 4; mi++)
                #pragma unroll
                for (int ni = 0; ni < 4; ni++)
                    mma_f16(acc[mi][ni], af[mi][0], af[mi][1], af[mi][2], af[mi][3],
                            bf[ni][0], bf[ni][1]);
        }
    }

    // ---- epilogue: bias, write Y (half), column stats ----
    float2 bb2[4];
    #pragma unroll
    for (int ni = 0; ni < 4; ni++)
        bb2[ni] = *reinterpret_cast<const float2*>(&bias[wn * 32 + ni * 8 + tq * 2]);
    #pragma unroll
    for (int mi = 0; mi < 4; mi++)
        #pragma unroll
        for (int ni = 0; ni < 4; ni++) {
            acc[mi][ni][0] += bb2[ni].x; acc[mi][ni][1] += bb2[ni].y;
            acc[mi][ni][2] += bb2[ni].x; acc[mi][ni][3] += bb2[ni].y;
        }

    __half* __restrict__ Y = mat ? d_Yh1 : d_Yh0;
    const int colbase = nblk * 128 + wn * 32;
    #pragma unroll
    for (int mi = 0; mi < 4; mi++) {
        const int R0 = row0 + wm * 64 + mi * 16 + g;
        #pragma unroll
        for (int ni = 0; ni < 4; ni++) {
            const int gc = colbase + ni * 8 + tq * 2;
            *reinterpret_cast<unsigned*>(&Y[R0 * 256 + gc])       = hpack(acc[mi][ni][0], acc[mi][ni][1]);
            *reinterpret_cast<unsigned*>(&Y[(R0 + 8) * 256 + gc]) = hpack(acc[mi][ni][2], acc[mi][ni][3]);
        }
    }

    __syncthreads();
    float* ssum = reinterpret_cast<float*>(sm);       // [2][128]
    float* ssq  = ssum + 256;
    #pragma unroll
    for (int ni = 0; ni < 4; ni++) {
        float s0 = 0.f, s1 = 0.f, q0 = 0.f, q1 = 0.f;
        #pragma unroll
        for (int mi = 0; mi < 4; mi++) {
            const float v0 = acc[mi][ni][0], v1 = acc[mi][ni][1];
            const float v2 = acc[mi][ni][2], v3 = acc[mi][ni][3];
            s0 += v0 + v2; s1 += v1 + v3;
            q0 += v0 * v0 + v2 * v2; q1 += v1 * v1 + v3 * v3;
        }
        #pragma unroll
        for (int off = 4; off < 32; off <<= 1) {
            s0 += __shfl_xor_sync(0xffffffffu, s0, off);
            s1 += __shfl_xor_sync(0xffffffffu, s1, off);
            q0 += __shfl_xor_sync(0xffffffffu, q0, off);
            q1 += __shfl_xor_sync(0xffffffffu, q1, off);
        }
        if (lane < 4) {
            const int lcol = wn * 32 + ni * 8 + tq * 2;
            ssum[wm * 128 + lcol] = s0;  ssum[wm * 128 + lcol + 1] = s1;
            ssq [wm * 128 + lcol] = q0;  ssq [wm * 128 + lcol + 1] = q1;
        }
    }
    __syncthreads();
    if (tid < 128) {
        const int gidx = (mat * MB + rb) * 256 + nblk * 128 + tid;
        d_psum  [gidx] = ssum[tid] + ssum[128 + tid];
        d_psumsq[gidx] = ssq [tid] + ssq [128 + tid];
    }
}

// ============================================================================
// Kernels 3/4: deterministic stat reduction -> BN scale/shift
// ============================================================================
__global__ void stats_partial()   // grid 128
{
    const int mat = blockIdx.x >> 6;
    const int sl  = blockIdx.x & 63;
    const int col = threadIdx.x;
    float s = 0.f, q = 0.f;
    const int rb0 = sl * (MB / 64);
    for (int rbi = rb0; rbi < rb0 + (MB / 64); rbi++) {
        s += d_psum  [(mat * MB + rbi) * 256 + col];
        q += d_psumsq[(mat * MB + rbi) * 256 + col];
    }
    d_psum2  [blockIdx.x * 256 + col] = s;
    d_psumsq2[blockIdx.x * 256 + col] = q;
}

__global__ void stats_final(const float* __restrict__ g0, const float* __restrict__ be0,
                            const float* __restrict__ g1, const float* __restrict__ be1)
{
    const int mat = blockIdx.x;
    const int col = threadIdx.x;
    float s = 0.f, q = 0.f;
    #pragma unroll
    for (int sl = 0; sl < 64; sl++) {
        s += d_psum2  [(mat * 64 + sl) * 256 + col];
        q += d_psumsq2[(mat * 64 + sl) * 256 + col];
    }
    const float inv  = 1.0f / (float)NROWS;
    const float mean = s * inv;
    const float var  = fmaxf(q * inv - mean * mean, 0.f);
    const float* gg = mat ? g1 : g0;
    const float* bb = mat ? be1 : be0;
    const float sc = gg[col] * rsqrtf(var + 1e-5f);
    const float sh = bb[col] - mean * sc;
    d_bnscale[mat * 256 + col] = sc;
    d_bnshift[mat * 256 + col] = sh;
    d_bns_h[mat * 256 + col] = __float2half(sc);
    d_bnh_h[mat * 256 + col] = __float2half(sh);
}

// ============================================================================
// Kernel 5: merged fp16 MMA merge GEMM: tile 128x256, 512 threads, BK=64
// grid (MB), 16 warps, pipelined BN pass: 1 sync per chunk
// ============================================================================
__global__ __launch_bounds__(512, 1)
void gemm2(const float* __restrict__ bm)
{
    extern __shared__ char sm[];
    const uint32_t sa = (uint32_t)__cvta_generic_to_shared(sm);
    __half2* bns2 = reinterpret_cast<__half2*>(sm + G2_BN);          // 256 half2
    __half2* bnh2 = reinterpret_cast<__half2*>(sm + G2_BN + 1024);   // 256 half2

    const int tid = threadIdx.x, lane = tid & 31, wid = tid >> 5;
    const int wm = wid >> 3, wn = wid & 7;
    const int g = lane >> 2, tq = lane & 3;
    const int row0 = blockIdx.x * 128;

    {
        const unsigned* s_src = reinterpret_cast<const unsigned*>(d_bns_h);
        const unsigned* h_src = reinterpret_cast<const unsigned*>(d_bnh_h);
        if (tid < 256) {
            reinterpret_cast<unsigned*>(bns2)[tid] = s_src[tid];
            reinterpret_cast<unsigned*>(bnh2)[tid] = h_src[tid];
        }
    }

    const int xr   = (lane & 7) << 4;
    const int al16 = (lane >> 4) * 16;
    const int bl16 = ((lane >> 3) & 1) * 16;
    const uint32_t aRow = (uint32_t)((wm * 64 + (lane & 15)) * 128);
    const uint32_t bRow = (uint32_t)((wn * 32 + (lane & 7) + ((lane >> 4) << 3)) * 128);

    const int pcb = (tid & 7) * 16;
    const int pch = (tid & 7) * 8;

    auto issue = [&](int s) {
        const uint32_t araw = sa + G2_ARAW + (s % 3) * 16384;
        const uint32_t bb   = sa + G2_Bb   + (s & 3) * 32768;
        const int kt = 64 * s;
        const __half* __restrict__ Ys = (kt < 256) ? d_Yh0 : d_Yh1;
        const int ko = kt & 255;
        #pragma unroll
        for (int j = 0; j < 2; j++) {
            const int row = (tid + 512 * j) >> 3;
            cp16(araw + (uint32_t)(row * 128 + (pcb ^ ((row & 7) << 4))),
                 Ys + (row0 + row) * 256 + ko + pch);
        }
        #pragma unroll
        for (int j = 0; j < 4; j++) {
            const int row = (tid + 512 * j) >> 3;
            cp16(bb + (uint32_t)(row * 128 + (pcb ^ ((row & 7) << 4))),
                 d_Wmh + row * 512 + kt + pch);
        }
    };

    const __half2 z2 = __float2half2_rn(0.f);

    auto bnpass = [&](int s) {
        char* araw = sm + G2_ARAW + (s % 3) * 16384;
        char* ah   = sm + G2_AH   + (s & 1) * 16384;
        const int kt = 64 * s;
        #pragma unroll
        for (int j = 0; j < 2; j++) {
            const int w = tid + 512 * j;
            const int row = w >> 3, c = w & 7;
            const uint32_t off = (uint32_t)(row * 128 + ((c * 16) ^ ((row & 7) << 4)));
            const __half2* rp = reinterpret_cast<const __half2*>(araw + off);
            __half2* wp = reinterpret_cast<__half2*>(ah + off);
            const int si = (kt >> 1) + c * 4;
            const __half2 s0 = bns2[si], s1 = bns2[si + 1], s2 = bns2[si + 2], s3 = bns2[si + 3];
            const __half2 h0 = bnh2[si], h1 = bnh2[si + 1], h2 = bnh2[si + 2], h3 = bnh2[si + 3];
            __half2 v0 = rp[0], v1 = rp[1], v2 = rp[2], v3 = rp[3];
            v0 = __hmax2(__hfma2(v0, s0, h0), z2);
            v1 = __hmax2(__hfma2(v1, s1, h1), z2);
            v2 = __hmax2(__hfma2(v2, s2, h2), z2);
            v3 = __hmax2(__hfma2(v3, s3, h3), z2);
            wp[0] = v0; wp[1] = v1; wp[2] = v2; wp[3] = v3;
        }
    };

    float acc[4][4][4];
    #pragma unroll
    for (int mi = 0; mi < 4; mi++)
        #pragma unroll
        for (int ni = 0; ni < 4; ni++)
            #pragma unroll
            for (int e = 0; e < 4; e++) acc[mi][ni][e] = 0.f;

    issue(0); cp_commit();
    issue(1); cp_commit();
    issue(2); cp_commit();
    cp_wait<2>();
    __syncthreads();       // bn consts + stage 0 visible
    bnpass(0);

    #pragma unroll 1
    for (int i = 0; i < 8; i++) {
        if (i < 6) cp_wait<1>(); else cp_wait<0>();
        __syncthreads();   // orders bnpass(i) writes + stage(i+1) arrival

        if (i + 1 < 8) bnpass(i + 1);
        if (i + 3 < 8) { issue(i + 3); cp_commit(); }

        const uint32_t ah = sa + G2_AH + (i & 1) * 16384;
        const uint32_t bb = sa + G2_Bb + (i & 3) * 32768;
        #pragma unroll
        for (int kc2 = 0; kc2 < 128; kc2 += 32) {
            const int ac = (kc2 + al16) ^ xr;
            const int bc = (kc2 + bl16) ^ xr;
            unsigned af[4][4], bf[4][2];
            #pragma unroll
            for (int mi = 0; mi < 4; mi++)
                ldsm4(af[mi][0], af[mi][1], af[mi][2], af[mi][3],
                      ah + aRow + mi * 2048 + ac);
            ldsm4(bf[0][0], bf[0][1], bf[1][0], bf[1][1], bb + bRow + bc);
            ldsm4(bf[2][0], bf[2][1], bf[3][0], bf[3][1], bb + bRow + 2048 + bc);
            #pragma unroll
            for (int mi = 0; mi < 4; mi++)
                #pragma unroll
                for (int ni = 0; ni < 4; ni++)
                    mma_f16(acc[mi][ni], af[mi][0], af[mi][1], af[mi][2], af[mi][3],
                            bf[ni][0], bf[ni][1]);
        }
    }

    // ---- epilogue: bias, 16-way wu dot, combine 8 warp partials, write d_st ----
    #pragma unroll
    for (int ni = 0; ni < 4; ni++) {
        const float2 bb = *reinterpret_cast<const float2*>(&bm[wn * 32 + ni * 8 + tq * 2]);
        #pragma unroll
        for (int mi = 0; mi < 4; mi++) {
            acc[mi][ni][0] += bb.x; acc[mi][ni][1] += bb.y;
            acc[mi][ni][2] += bb.x; acc[mi][ni][3] += bb.y;
        }
    }

    __syncthreads();
    float* wuS = reinterpret_cast<float*>(sm);           // [16][256] = 16 KB
    float* stS = reinterpret_cast<float*>(sm) + 4096;    // [8 wn][128 rows][16 h] = 64 KB
    #pragma unroll
    for (int j = 0; j < 8; j++) wuS[tid + 512 * j] = d_wu[tid + 512 * j];
    __syncthreads();

    #pragma unroll
    for (int h = 0; h < 16; h++) {
        float2 wv[4];
        #pragma unroll
        for (int ni = 0; ni < 4; ni++)
            wv[ni] = *reinterpret_cast<const float2*>(&wuS[h * 256 + wn * 32 + ni * 8 + tq * 2]);
        #pragma unroll
        for (int mi = 0; mi < 4; mi++) {
            float p0 = 0.f, p1 = 0.f;
            #pragma unroll
            for (int ni = 0; ni < 4; ni++) {
                p0 += acc[mi][ni][0] * wv[ni].x + acc[mi][ni][1] * wv[ni].y;
                p1 += acc[mi][ni][2] * wv[ni].x + acc[mi][ni][3] * wv[ni].y;
            }
            p0 += __shfl_xor_sync(0xffffffffu, p0, 1);
            p0 += __shfl_xor_sync(0xffffffffu, p0, 2);
            p1 += __shfl_xor_sync(0xffffffffu, p1, 1);
            p1 += __shfl_xor_sync(0xffffffffu, p1, 2);
            if (tq == 0) {
                const int rl = wm * 64 + mi * 16 + g;
                stS[wn * 2048 + rl * 16 + h]       = p0;
                stS[wn * 2048 + (rl + 8) * 16 + h] = p1;
            }
        }
    }
    __syncthreads();
    {
        const int rowl = tid >> 2, hh = (tid & 3) * 4;
        float v[4];
        #pragma unroll
        for (int j = 0; j < 4; j++) {
            float s = 0.f;
            #pragma unroll
            for (int w = 0; w < 8; w++) s += stS[w * 2048 + rowl * 16 + hh + j];
            v[j] = s;
        }
        *reinterpret_cast<float4*>(&d_st[(row0 + rowl) * 16 + hh]) =
            make_float4(v[0], v[1], v[2], v[3]);
    }
}

// ============================================================================
// Kernel 6: per-group softmax-weighted mean + tanh readout
// ============================================================================
__global__ void groups_kernel(float* __restrict__ out)
{
    __shared__ float sb[NPGC * 16];
    __shared__ float hv[8];
    const int g = blockIdx.x;
    const int tid = threadIdx.x;
    const float* __restrict__ b0 = &d_st[g * (NPGC * 16)];
    for (int i = tid; i < NPGC * 16; i += 256) sb[i] = b0[i];
    __syncthreads();

    const int h    = tid >> 5;
    const int lane = tid & 31;

    float mx = -1e30f;
    for (int r = lane; r < NPGC; r += 32) mx = fmaxf(mx, sb[r * 16 + h]);
    #pragma unroll
    for (int off = 16; off; off >>= 1) mx = fmaxf(mx, __shfl_xor_sync(0xffffffffu, mx, off));

    float num = 0.f, den = 0.f;
    for (int r = lane; r < NPGC; r += 32) {
        const float e = expf(sb[r * 16 + h] - mx);
        num = fmaf(e, sb[r * 16 + 8 + h], num);
        den += e;
    }
    #pragma unroll
    for (int off = 16; off; off >>= 1) {
        num += __shfl_xor_sync(0xffffffffu, num, off);
        den += __shfl_xor_sync(0xffffffffu, den, off);
    }
    if (lane == 0) hv[h] = num / den;
    __syncthreads();

    if (tid == 0) {
        float s = d_cconst[0];
        #pragma unroll
        for (int i = 0; i < 8; i++) s += hv[i];
        out[g] = tanhf(s);
    }
}

// ============================================================================
extern "C" void kernel_launch(void* const* d_in, const int* in_sizes, int n_in,
                              void* d_out, int out_size)
{
    const float* x0   = (const float*)d_in[0];
    const float* x1   = (const float*)d_in[1];
    const float* p0W  = (const float*)d_in[3];
    const float* p0b  = (const float*)d_in[4];
    const float* p0g  = (const float*)d_in[5];
    const float* p0be = (const float*)d_in[6];
    const float* p1W  = (const float*)d_in[7];
    const float* p1b  = (const float*)d_in[8];
    const float* p1g  = (const float*)d_in[9];
    const float* p1be = (const float*)d_in[10];
    const float* mW   = (const float*)d_in[11];
    const float* mb   = (const float*)d_in[12];
    const float* ipW  = (const float*)d_in[13];
    const float* ipb  = (const float*)d_in[14];
    const float* opW  = (const float*)d_in[15];
    const float* opb  = (const float*)d_in[16];
    const float* rW   = (const float*)d_in[17];
    const float* rb   = (const float*)d_in[18];
    float* out = (float*)d_out;

    cudaFuncSetAttribute(gemm1, cudaFuncAttributeMaxDynamicSharedMemorySize, SMEM1g);
    cudaFuncSetAttribute(gemm2, cudaFuncAttributeMaxDynamicSharedMemorySize, SMEM2g);

    prep_kernel<<<1, 256>>>(ipW, ipb, opW, opb, rW, rb);
    convert_w<<<256, 256>>>(p0W, p1W, mW);
    gemm1<<<dim3(2, MB, 2), 256, SMEM1g>>>(x0, x1, p0b, p1b);
    stats_partial<<<128, 256>>>();
    stats_final<<<2, 256>>>(p0g, p0be, p1g, p1be);
    gemm2<<<MB, 512, SMEM2g>>>(mb);
    groups_kernel<<<NG, 256>>>(out);
}

// round 15
// speedup vs baseline: 1.0993x; 1.0023x over previous
#include <cuda_runtime.h>
#include <cuda_fp16.h>
#include <cstdint>
#include <math.h>

#define NROWS 204800
#define NG    2048
#define NPGC  100
#define MB    1600            // NROWS / 128

// ---- scratch (device globals; allocation forbidden) ----
__device__ __half d_Yh0[NROWS * 256];
__device__ __half d_Yh1[NROWS * 256];
__device__ __half d_Wh0[256 * 256];
__device__ __half d_Wh1[256 * 256];
__device__ __half d_Wmh[256 * 512];
__device__ float d_psum  [2 * MB * 256];
__device__ float d_psumsq[2 * MB * 256];
__device__ float d_psum2  [128 * 256];
__device__ float d_psumsq2[128 * 256];
__device__ float d_bnscale[512];
__device__ float d_bnshift[512];
__device__ __half d_bns_h[512];
__device__ __half d_bnh_h[512];
__device__ float d_qv[256];
__device__ float d_r2p[8][256];
__device__ float d_r2v[256];
__device__ float d_wu[16 * 256];        // rows 0..7: ws_h ; rows 8..15: u_h
__device__ float d_cconst[1];
__device__ float d_stp[2][NROWS * 16];  // per-nblk partial [scores(8)|t(8)]

// ---- helpers ----
__device__ __forceinline__ unsigned hpack(float a, float b) {
    __half2 h = __floats2half2_rn(a, b);
    return *reinterpret_cast<unsigned*>(&h);
}
__device__ __forceinline__ void mma_f16(float c[4],
    unsigned a0, unsigned a1, unsigned a2, unsigned a3, unsigned b0, unsigned b1)
{
    asm volatile(
        "mma.sync.aligned.m16n8k16.row.col.f32.f16.f16.f32 "
        "{%0,%1,%2,%3},{%4,%5,%6,%7},{%8,%9},{%0,%1,%2,%3};"
        : "+f"(c[0]), "+f"(c[1]), "+f"(c[2]), "+f"(c[3])
        : "r"(a0), "r"(a1), "r"(a2), "r"(a3), "r"(b0), "r"(b1));
}
__device__ __forceinline__ void ldsm4(unsigned& r0, unsigned& r1, unsigned& r2, unsigned& r3,
                                      uint32_t addr)
{
    asm volatile("ldmatrix.sync.aligned.m8n8.x4.shared.b16 {%0,%1,%2,%3}, [%4];"
        : "=r"(r0), "=r"(r1), "=r"(r2), "=r"(r3) : "r"(addr));
}
__device__ __forceinline__ void cp16(uint32_t dst, const void* src) {
    asm volatile("cp.async.cg.shared.global [%0], [%1], 16;" :: "r"(dst), "l"(src) : "memory");
}
__device__ __forceinline__ void cp_commit() {
    asm volatile("cp.async.commit_group;" ::: "memory");
}
template<int N> __device__ __forceinline__ void cp_wait() {
    asm volatile("cp.async.wait_group %0;" :: "n"(N) : "memory");
}

// ---- gemm1 staging rings: Ah x2 (80B rows), B x4 (80B rows), Af32 x3 (128B rows) ----
constexpr int G1_AH   = 0;                 // 2 * 10240
constexpr int G1_B    = 20480;             // 4 * 10240
constexpr int G1_AF   = 61440;             // 3 * 16384
constexpr int SMEM1g  = 61440 + 49152;     // 110592

// ---- gemm2 split rings (tile 128x128, BK=32): Ah x2, B x4, Araw x3 (all 80B rows) ----
constexpr int H2_AH   = 0;                 // 2 * 10240
constexpr int H2_B    = 20480;             // 4 * 10240
constexpr int H2_AR   = 61440;             // 3 * 10240
constexpr int H2_BN   = 92160;             // 2048
constexpr int SMEM2g  = 94208;

// ============================================================================
// convert weights to half
// ============================================================================
__global__ void convert_w(const float* __restrict__ W0, const float* __restrict__ W1,
                          const float* __restrict__ Wm)
{
    int t = blockIdx.x * 256 + threadIdx.x;    // 0..65535
    const float* src; __half* dst; int k;
    if (t < 16384)      { src = W0; dst = d_Wh0; k = t; }
    else if (t < 32768) { src = W1; dst = d_Wh1; k = t - 16384; }
    else                { src = Wm; dst = d_Wmh; k = t - 32768; }
    const float4 v = reinterpret_cast<const float4*>(src)[k];
    uint2 w; w.x = hpack(v.x, v.y); w.y = hpack(v.z, v.w);
    reinterpret_cast<uint2*>(dst)[k] = w;
}

// ============================================================================
// prep (parallelized): q / r2 partials -> combine + cconst -> wu rows
// ============================================================================
__global__ void prep_a(const float* __restrict__ ipW, const float* __restrict__ ipb,
                       const float* __restrict__ opW, const float* __restrict__ rW)
{
    const int b = blockIdx.x, c = threadIdx.x;
    if (b == 8) {
        float s = 0.f;
        for (int k = 0; k < 256; k += 4) {
            float4 v = *reinterpret_cast<const float4*>(&ipW[c * 256 + k]);
            s += v.x + v.y + v.z + v.w;
        }
        d_qv[c] = (s + ipb[c]) * 0.17677669529663687f;
    } else {
        float s = 0.f;
        #pragma unroll 8
        for (int k = b * 32; k < b * 32 + 32; k++)
            s += rW[k] * opW[k * 256 + c];
        d_r2p[b][c] = s;
    }
}

__global__ void prep_b(const float* __restrict__ ipb, const float* __restrict__ opb,
                       const float* __restrict__ rW,  const float* __restrict__ rb)
{
    __shared__ float red[256];
    const int c = threadIdx.x;
    float r2 = 0.f;
    #pragma unroll
    for (int b = 0; b < 8; b++) r2 += d_r2p[b][c];
    d_r2v[c] = r2;
    red[c] = ipb[512 + c] * r2 + rW[c] * opb[c];
    __syncthreads();
    for (int off = 128; off; off >>= 1) {
        if (c < off) red[c] += red[c + off];
        __syncthreads();
    }
    if (c == 0) d_cconst[0] = red[0] + rb[0];
}

__global__ void wu_kernel(const float* __restrict__ ipW)
{
    const int h2 = blockIdx.x, c = threadIdx.x;
    const int h = h2 & 7;
    const float* coeff = (h2 < 8) ? d_qv : d_r2v;
    const int rbase = (h2 < 8) ? 256 : 512;
    float s = 0.f;
    #pragma unroll 8
    for (int d = 0; d < 32; d++)
        s += coeff[h * 32 + d] * ipW[(rbase + h * 32 + d) * 256 + c];
    d_wu[h2 * 256 + c] = s;
}

// ============================================================================
// Kernel 2: fused fp32->half + fp16 MMA GEMM  Y = X @ W^T + b  + column stats
// grid (2 nblk, MB, 2 mat), 256 threads, BK=32, 8 chunks, pipelined convert
// ============================================================================
__global__ __launch_bounds__(256, 2)
void gemm1(const float* __restrict__ X0, const float* __restrict__ X1,
           const float* __restrict__ B0, const float* __restrict__ B1)
{
    extern __shared__ char sm[];
    const uint32_t sa = (uint32_t)__cvta_generic_to_shared(sm);

    const int nblk = blockIdx.x;
    const int rb   = blockIdx.y;
    const int mat  = blockIdx.z;
    const float*  __restrict__ Xf = mat ? X1 : X0;
    const __half* __restrict__ Wh = mat ? d_Wh1 : d_Wh0;
    const float*  __restrict__ bias = (mat ? B1 : B0) + nblk * 128;

    const int tid = threadIdx.x, lane = tid & 31, wid = tid >> 5;
    const int wm = wid >> 2, wn = wid & 3;
    const int g = lane >> 2, tq = lane & 3;
    const int row0 = rb * 128;

    const __half* __restrict__ Brow0 = Wh + nblk * 128 * 256;

    const uint32_t aOff = (uint32_t)((wm * 64 + (lane & 15)) * 80 + ((lane >> 4) * 8) * 2);
    const uint32_t bOff = (uint32_t)((wn * 32 + (lane & 7) + ((lane >> 4) << 3)) * 80
                                     + (((lane >> 3) & 1) * 8) * 2);

    auto issue = [&](int s) {
        const uint32_t af = sa + G1_AF + (s % 3) * 16384;
        const uint32_t bb = sa + G1_B  + (s & 3) * 10240;
        const int kt = 32 * s;
        #pragma unroll
        for (int jj = 0; jj < 4; jj++) {
            const int p = tid + 256 * jj;
            const int row = p >> 3, c = p & 7;
            cp16(af + (uint32_t)(row * 128 + ((c * 16) ^ ((row & 7) << 4))),
                 Xf + (row0 + row) * 256 + kt + c * 4);
        }
        #pragma unroll
        for (int jj = 0; jj < 2; jj++) {
            const int p = tid + 256 * jj;
            const int row = p >> 2, c = p & 3;
            cp16(bb + (uint32_t)(row * 80 + c * 16),
                 Brow0 + row * 256 + kt + c * 8);
        }
    };

    auto convert = [&](int s) {
        char* af = sm + G1_AF + (s % 3) * 16384;
        char* ah = sm + G1_AH + (s & 1) * 10240;
        #pragma unroll
        for (int jj = 0; jj < 2; jj++) {
            const int w = tid + 256 * jj;
            const int row = w >> 2, c8 = w & 3;
            const int xo = (row & 7) << 4;
            const float4 f0 = *reinterpret_cast<const float4*>(af + row * 128 + ((c8 * 32) ^ xo));
            const float4 f1 = *reinterpret_cast<const float4*>(af + row * 128 + ((c8 * 32 + 16) ^ xo));
            uint4 hv;
            hv.x = hpack(f0.x, f0.y); hv.y = hpack(f0.z, f0.w);
            hv.z = hpack(f1.x, f1.y); hv.w = hpack(f1.z, f1.w);
            *reinterpret_cast<uint4*>(ah + row * 80 + c8 * 16) = hv;
        }
    };

    float acc[4][4][4];
    #pragma unroll
    for (int mi = 0; mi < 4; mi++)
        #pragma unroll
        for (int ni = 0; ni < 4; ni++)
            #pragma unroll
            for (int e = 0; e < 4; e++) acc[mi][ni][e] = 0.f;

    issue(0); cp_commit();
    issue(1); cp_commit();
    issue(2); cp_commit();
    cp_wait<2>();
    __syncthreads();
    convert(0);

    #pragma unroll 1
    for (int i = 0; i < 8; i++) {
        if (i < 6) cp_wait<1>(); else cp_wait<0>();
        __syncthreads();

        if (i + 1 < 8) convert(i + 1);
        if (i + 3 < 8) { issue(i + 3); cp_commit(); }

        const uint32_t ah = sa + G1_AH + (i & 1) * 10240;
        const uint32_t bb = sa + G1_B  + (i & 3) * 10240;
        #pragma unroll
        for (int kc = 0; kc < 32; kc += 16) {
            unsigned af[4][4], bf[4][2];
            #pragma unroll
            for (int mi = 0; mi < 4; mi++)
                ldsm4(af[mi][0], af[mi][1], af[mi][2], af[mi][3],
                      ah + aOff + mi * 16 * 80 + kc * 2);
            ldsm4(bf[0][0], bf[0][1], bf[1][0], bf[1][1], bb + bOff + kc * 2);
            ldsm4(bf[2][0], bf[2][1], bf[3][0], bf[3][1], bb + bOff + 16 * 80 + kc * 2);
            #pragma unroll
            for (int mi = 0; mi < 4; mi++)
                #pragma unroll
                for (int ni = 0; ni < 4; ni++)
                    mma_f16(acc[mi][ni], af[mi][0], af[mi][1], af[mi][2], af[mi][3],
                            bf[ni][0], bf[ni][1]);
        }
    }

    // ---- epilogue: bias, write Y (half), column stats ----
    float2 bb2[4];
    #pragma unroll
    for (int ni = 0; ni < 4; ni++)
        bb2[ni] = *reinterpret_cast<const float2*>(&bias[wn * 32 + ni * 8 + tq * 2]);
    #pragma unroll
    for (int mi = 0; mi < 4; mi++)
        #pragma unroll
        for (int ni = 0; ni < 4; ni++) {
            acc[mi][ni][0] += bb2[ni].x; acc[mi][ni][1] += bb2[ni].y;
            acc[mi][ni][2] += bb2[ni].x; acc[mi][ni][3] += bb2[ni].y;
        }

    __half* __restrict__ Y = mat ? d_Yh1 : d_Yh0;
    const int colbase = nblk * 128 + wn * 32;
    #pragma unroll
    for (int mi = 0; mi < 4; mi++) {
        const int R0 = row0 + wm * 64 + mi * 16 + g;
        #pragma unroll
        for (int ni = 0; ni < 4; ni++) {
            const int gc = colbase + ni * 8 + tq * 2;
            *reinterpret_cast<unsigned*>(&Y[R0 * 256 + gc])       = hpack(acc[mi][ni][0], acc[mi][ni][1]);
            *reinterpret_cast<unsigned*>(&Y[(R0 + 8) * 256 + gc]) = hpack(acc[mi][ni][2], acc[mi][ni][3]);
        }
    }

    __syncthreads();
    float* ssum = reinterpret_cast<float*>(sm);       // [2][128]
    float* ssq  = ssum + 256;
    #pragma unroll
    for (int ni = 0; ni < 4; ni++) {
        float s0 = 0.f, s1 = 0.f, q0 = 0.f, q1 = 0.f;
        #pragma unroll
        for (int mi = 0; mi < 4; mi++) {
            const float v0 = acc[mi][ni][0], v1 = acc[mi][ni][1];
            const float v2 = acc[mi][ni][2], v3 = acc[mi][ni][3];
            s0 += v0 + v2; s1 += v1 + v3;
            q0 += v0 * v0 + v2 * v2; q1 += v1 * v1 + v3 * v3;
        }
        #pragma unroll
        for (int off = 4; off < 32; off <<= 1) {
            s0 += __shfl_xor_sync(0xffffffffu, s0, off);
            s1 += __shfl_xor_sync(0xffffffffu, s1, off);
            q0 += __shfl_xor_sync(0xffffffffu, q0, off);
            q1 += __shfl_xor_sync(0xffffffffu, q1, off);
        }
        if (lane < 4) {
            const int lcol = wn * 32 + ni * 8 + tq * 2;
            ssum[wm * 128 + lcol] = s0;  ssum[wm * 128 + lcol + 1] = s1;
            ssq [wm * 128 + lcol] = q0;  ssq [wm * 128 + lcol + 1] = q1;
        }
    }
    __syncthreads();
    if (tid < 128) {
        const int gidx = (mat * MB + rb) * 256 + nblk * 128 + tid;
        d_psum  [gidx] = ssum[tid] + ssum[128 + tid];
        d_psumsq[gidx] = ssq [tid] + ssq [128 + tid];
    }
}

// ============================================================================
// Kernels 3/4: deterministic stat reduction -> BN scale/shift
// ============================================================================
__global__ void stats_partial()   // grid 128
{
    const int mat = blockIdx.x >> 6;
    const int sl  = blockIdx.x & 63;
    const int col = threadIdx.x;
    float s = 0.f, q = 0.f;
    const int rb0 = sl * (MB / 64);
    for (int rbi = rb0; rbi < rb0 + (MB / 64); rbi++) {
        s += d_psum  [(mat * MB + rbi) * 256 + col];
        q += d_psumsq[(mat * MB + rbi) * 256 + col];
    }
    d_psum2  [blockIdx.x * 256 + col] = s;
    d_psumsq2[blockIdx.x * 256 + col] = q;
}

__global__ void stats_final(const float* __restrict__ g0, const float* __restrict__ be0,
                            const float* __restrict__ g1, const float* __restrict__ be1)
{
    const int mat = blockIdx.x;
    const int col = threadIdx.x;
    float s = 0.f, q = 0.f;
    #pragma unroll
    for (int sl = 0; sl < 64; sl++) {
        s += d_psum2  [(mat * 64 + sl) * 256 + col];
        q += d_psumsq2[(mat * 64 + sl) * 256 + col];
    }
    const float inv  = 1.0f / (float)NROWS;
    const float mean = s * inv;
    const float var  = fmaxf(q * inv - mean * mean, 0.f);
    const float* gg = mat ? g1 : g0;
    const float* bb = mat ? be1 : be0;
    const float sc = gg[col] * rsqrtf(var + 1e-5f);
    const float sh = bb[col] - mean * sc;
    d_bnscale[mat * 256 + col] = sc;
    d_bnshift[mat * 256 + col] = sh;
    d_bns_h[mat * 256 + col] = __float2half(sc);
    d_bnh_h[mat * 256 + col] = __float2half(sh);
}

// ============================================================================
// Kernel 5: split merge GEMM: grid (2 nblk, MB), 256 threads, tile 128x128,
// BK=32, 16 chunks, pipelined BN pass (1 sync/chunk), 2 CTAs/SM
// ============================================================================
__global__ __launch_bounds__(256, 2)
void gemm2(const float* __restrict__ bm)
{
    extern __shared__ char sm[];
    const uint32_t sa = (uint32_t)__cvta_generic_to_shared(sm);
    __half2* bns2 = reinterpret_cast<__half2*>(sm + H2_BN);          // 256 half2
    __half2* bnh2 = reinterpret_cast<__half2*>(sm + H2_BN + 1024);   // 256 half2

    const int nblk = blockIdx.x;
    const int rb   = blockIdx.y;
    const int tid = threadIdx.x, lane = tid & 31, wid = tid >> 5;
    const int wm = wid >> 2, wn = wid & 3;
    const int g = lane >> 2, tq = lane & 3;
    const int row0 = rb * 128;

    {
        const unsigned* s_src = reinterpret_cast<const unsigned*>(d_bns_h);
        const unsigned* h_src = reinterpret_cast<const unsigned*>(d_bnh_h);
        reinterpret_cast<unsigned*>(bns2)[tid] = s_src[tid];
        reinterpret_cast<unsigned*>(bnh2)[tid] = h_src[tid];
    }

    const __half* __restrict__ Brow0 = d_Wmh + nblk * 128 * 512;

    const uint32_t aOff = (uint32_t)((wm * 64 + (lane & 15)) * 80 + ((lane >> 4) * 8) * 2);
    const uint32_t bOff = (uint32_t)((wn * 32 + (lane & 7) + ((lane >> 4) << 3)) * 80
                                     + (((lane >> 3) & 1) * 8) * 2);

    auto issue = [&](int s) {
        const uint32_t ar = sa + H2_AR + (s % 3) * 10240;
        const uint32_t bb = sa + H2_B  + (s & 3) * 10240;
        const int kt = 32 * s;
        const __half* __restrict__ Ys = (kt < 256) ? d_Yh0 : d_Yh1;
        const int ko = kt & 255;
        #pragma unroll
        for (int jj = 0; jj < 2; jj++) {
            const int p = tid + 256 * jj;
            const int row = p >> 2, c = p & 3;
            cp16(ar + (uint32_t)(row * 80 + c * 16),
                 Ys + (row0 + row) * 256 + ko + c * 8);
        }
        #pragma unroll
        for (int jj = 0; jj < 2; jj++) {
            const int p = tid + 256 * jj;
            const int row = p >> 2, c = p & 3;
            cp16(bb + (uint32_t)(row * 80 + c * 16),
                 Brow0 + row * 512 + kt + c * 8);
        }
    };

    const __half2 z2 = __float2half2_rn(0.f);

    auto bnpass = [&](int s) {
        char* ar = sm + H2_AR + (s % 3) * 10240;
        char* ah = sm + H2_AH + (s & 1) * 10240;
        const int kt = 32 * s;
        #pragma unroll
        for (int jj = 0; jj < 2; jj++) {
            const int w = tid + 256 * jj;
            const int row = w >> 2, c = w & 3;
            const uint32_t off = (uint32_t)(row * 80 + c * 16);
            const __half2* rp = reinterpret_cast<const __half2*>(ar + off);
            __half2* wp = reinterpret_cast<__half2*>(ah + off);
            const int si = (kt + c * 8) >> 1;
            const __half2 s0 = bns2[si], s1 = bns2[si + 1], s2 = bns2[si + 2], s3 = bns2[si + 3];
            const __half2 h0 = bnh2[si], h1 = bnh2[si + 1], h2 = bnh2[si + 2], h3 = bnh2[si + 3];
            __half2 v0 = rp[0], v1 = rp[1], v2 = rp[2], v3 = rp[3];
            v0 = __hmax2(__hfma2(v0, s0, h0), z2);
            v1 = __hmax2(__hfma2(v1, s1, h1), z2);
            v2 = __hmax2(__hfma2(v2, s2, h2), z2);
            v3 = __hmax2(__hfma2(v3, s3, h3), z2);
            wp[0] = v0; wp[1] = v1; wp[2] = v2; wp[3] = v3;
        }
    };

    float acc[4][4][4];
    #pragma unroll
    for (int mi = 0; mi < 4; mi++)
        #pragma unroll
        for (int ni = 0; ni < 4; ni++)
            #pragma unroll
            for (int e = 0; e < 4; e++) acc[mi][ni][e] = 0.f;

    issue(0); cp_commit();
    issue(1); cp_commit();
    issue(2); cp_commit();
    cp_wait<2>();
    __syncthreads();
    bnpass(0);

    #pragma unroll 1
    for (int i = 0; i < 16; i++) {
        if (i < 14) cp_wait<1>(); else cp_wait<0>();
        __syncthreads();

        if (i + 1 < 16) bnpass(i + 1);
        if (i + 3 < 16) { issue(i + 3); cp_commit(); }

        const uint32_t ah = sa + H2_AH + (i & 1) * 10240;
        const uint32_t bb = sa + H2_B  + (i & 3) * 10240;
        #pragma unroll
        for (int kc = 0; kc < 32; kc += 16) {
            unsigned af[4][4], bf[4][2];
            #pragma unroll
            for (int mi = 0; mi < 4; mi++)
                ldsm4(af[mi][0], af[mi][1], af[mi][2], af[mi][3],
                      ah + aOff + mi * 16 * 80 + kc * 2);
            ldsm4(bf[0][0], bf[0][1], bf[1][0], bf[1][1], bb + bOff + kc * 2);
            ldsm4(bf[2][0], bf[2][1], bf[3][0], bf[3][1], bb + bOff + 16 * 80 + kc * 2);
            #pragma unroll
            for (int mi = 0; mi < 4; mi++)
                #pragma unroll
                for (int ni = 0; ni < 4; ni++)
                    mma_f16(acc[mi][ni], af[mi][0], af[mi][1], af[mi][2], af[mi][3],
                            bf[ni][0], bf[ni][1]);
        }
    }

    // ---- epilogue: bias, 16-way wu dot, combine 4 warp partials, write d_stp ----
    #pragma unroll
    for (int ni = 0; ni < 4; ni++) {
        const float2 bb = *reinterpret_cast<const float2*>(&bm[nblk * 128 + wn * 32 + ni * 8 + tq * 2]);
        #pragma unroll
        for (int mi = 0; mi < 4; mi++) {
            acc[mi][ni][0] += bb.x; acc[mi][ni][1] += bb.y;
            acc[mi][ni][2] += bb.x; acc[mi][ni][3] += bb.y;
        }
    }

    __syncthreads();
    float* wuS = reinterpret_cast<float*>(sm);           // [16][128] = 8 KB
    float* stS = reinterpret_cast<float*>(sm) + 2048;    // [4 wn][128 rows][16 h] = 32 KB
    #pragma unroll
    for (int j = 0; j < 8; j++) {
        const int i2 = tid + 256 * j;
        const int h = i2 >> 7, c = i2 & 127;
        wuS[i2] = d_wu[h * 256 + nblk * 128 + c];
    }
    __syncthreads();

    #pragma unroll
    for (int h = 0; h < 16; h++) {
        float2 wv[4];
        #pragma unroll
        for (int ni = 0; ni < 4; ni++)
            wv[ni] = *reinterpret_cast<const float2*>(&wuS[h * 128 + wn * 32 + ni * 8 + tq * 2]);
        #pragma unroll
        for (int mi = 0; mi < 4; mi++) {
            float p0 = 0.f, p1 = 0.f;
            #pragma unroll
            for (int ni = 0; ni < 4; ni++) {
                p0 += acc[mi][ni][0] * wv[ni].x + acc[mi][ni][1] * wv[ni].y;
                p1 += acc[mi][ni][2] * wv[ni].x + acc[mi][ni][3] * wv[ni].y;
            }
            p0 += __shfl_xor_sync(0xffffffffu, p0, 1);
            p0 += __shfl_xor_sync(0xffffffffu, p0, 2);
            p1 += __shfl_xor_sync(0xffffffffu, p1, 1);
            p1 += __shfl_xor_sync(0xffffffffu, p1, 2);
            if (tq == 0) {
                const int rl = wm * 64 + mi * 16 + g;
                stS[wn * 2048 + rl * 16 + h]       = p0;
                stS[wn * 2048 + (rl + 8) * 16 + h] = p1;
            }
        }
    }
    __syncthreads();
    {
        const int rowl = tid >> 1, hh = (tid & 1) * 8;
        float v[8];
        #pragma unroll
        for (int j = 0; j < 8; j++) {
            v[j] = stS[rowl * 16 + hh + j] + stS[2048 + rowl * 16 + hh + j]
                 + stS[4096 + rowl * 16 + hh + j] + stS[6144 + rowl * 16 + hh + j];
        }
        float* dst = &d_stp[nblk][(row0 + rowl) * 16 + hh];
        *reinterpret_cast<float4*>(dst)     = make_float4(v[0], v[1], v[2], v[3]);
        *reinterpret_cast<float4*>(dst + 4) = make_float4(v[4], v[5], v[6], v[7]);
    }
}

// ============================================================================
// Kernel 6: per-group softmax-weighted mean + tanh readout
// ============================================================================
__global__ void groups_kernel(float* __restrict__ out)
{
    __shared__ float sb[NPGC * 16];
    __shared__ float hv[8];
    const int g = blockIdx.x;
    const int tid = threadIdx.x;
    const float* __restrict__ b0 = &d_stp[0][g * (NPGC * 16)];
    const float* __restrict__ b1 = &d_stp[1][g * (NPGC * 16)];
    for (int i = tid; i < NPGC * 16; i += 256) sb[i] = b0[i] + b1[i];
    __syncthreads();

    const int h    = tid >> 5;
    const int lane = tid & 31;

    float mx = -1e30f;
    for (int r = lane; r < NPGC; r += 32) mx = fmaxf(mx, sb[r * 16 + h]);
    #pragma unroll
    for (int off = 16; off; off >>= 1) mx = fmaxf(mx, __shfl_xor_sync(0xffffffffu, mx, off));

    float num = 0.f, den = 0.f;
    for (int r = lane; r < NPGC; r += 32) {
        const float e = expf(sb[r * 16 + h] - mx);
        num = fmaf(e, sb[r * 16 + 8 + h], num);
        den += e;
    }
    #pragma unroll
    for (int off = 16; off; off >>= 1) {
        num += __shfl_xor_sync(0xffffffffu, num, off);
        den += __shfl_xor_sync(0xffffffffu, den, off);
    }
    if (lane == 0) hv[h] = num / den;
    __syncthreads();

    if (tid == 0) {
        float s = d_cconst[0];
        #pragma unroll
        for (int i = 0; i < 8; i++) s += hv[i];
        out[g] = tanhf(s);
    }
}

// ============================================================================
extern "C" void kernel_launch(void* const* d_in, const int* in_sizes, int n_in,
                              void* d_out, int out_size)
{
    const float* x0   = (const float*)d_in[0];
    const float* x1   = (const float*)d_in[1];
    const float* p0W  = (const float*)d_in[3];
    const float* p0b  = (const float*)d_in[4];
    const float* p0g  = (const float*)d_in[5];
    const float* p0be = (const float*)d_in[6];
    const float* p1W  = (const float*)d_in[7];
    const float* p1b  = (const float*)d_in[8];
    const float* p1g  = (const float*)d_in[9];
    const float* p1be = (const float*)d_in[10];
    const float* mW   = (const float*)d_in[11];
    const float* mb   = (const float*)d_in[12];
    const float* ipW  = (const float*)d_in[13];
    const float* ipb  = (const float*)d_in[14];
    const float* opW  = (const float*)d_in[15];
    const float* opb  = (const float*)d_in[16];
    const float* rW   = (const float*)d_in[17];
    const float* rb   = (const float*)d_in[18];
    float* out = (float*)d_out;

    cudaFuncSetAttribute(gemm1, cudaFuncAttributeMaxDynamicSharedMemorySize, SMEM1g);
    cudaFuncSetAttribute(gemm2, cudaFuncAttributeMaxDynamicSharedMemorySize, SMEM2g);

    prep_a<<<9, 256>>>(ipW, ipb, opW, rW);
    prep_b<<<1, 256>>>(ipb, opb, rW, rb);
    wu_kernel<<<16, 256>>>(ipW);
    convert_w<<<256, 256>>>(p0W, p1W, mW);
    gemm1<<<dim3(2, MB, 2), 256, SMEM1g>>>(x0, x1, p0b, p1b);
    stats_partial<<<128, 256>>>();
    stats_final<<<2, 256>>>(p0g, p0be, p1g, p1be);
    gemm2<<<dim3(2, MB), 256, SMEM2g>>>(mb);
    groups_kernel<<<NG, 256>>>(out);
}

// round 16
// speedup vs baseline: 1.6736x; 1.5224x over previous
#include <cuda_runtime.h>
#include <cuda_fp16.h>
#include <cstdint>
#include <math.h>

#define NROWS 204800
#define NG    2048
#define NPGC  100
#define MB    1600            // NROWS / 128

// ---- scratch (device globals; allocation forbidden) ----
__device__ __half d_Yh0[NROWS * 256];
__device__ __half d_Yh1[NROWS * 256];
__device__ __half d_Wh0[256 * 256];
__device__ __half d_Wh1[256 * 256];
__device__ float d_psum  [2 * MB * 256];
__device__ float d_psumsq[2 * MB * 256];
__device__ float d_psum2  [128 * 256];
__device__ float d_psumsq2[128 * 256];
__device__ float d_bnscale[512];
__device__ float d_bnshift[512];
__device__ __half d_bns_h[512];
__device__ __half d_bnh_h[512];
__device__ float d_qv[256];
__device__ float d_r2p[8][256];
__device__ float d_r2v[256];
__device__ float d_wu[16 * 256];        // rows 0..7: ws_h ; rows 8..15: u_h
__device__ __align__(16) __half d_Wfh[16 * 512];   // Wfold: [h2][k]
__device__ float d_cfold[16];
__device__ float d_cconst[1];
__device__ float d_st[NROWS * 16];      // per row: [scores(8) | t(8)]

// ---- helpers ----
__device__ __forceinline__ unsigned hpack(float a, float b) {
    __half2 h = __floats2half2_rn(a, b);
    return *reinterpret_cast<unsigned*>(&h);
}
__device__ __forceinline__ void mma_f16(float c[4],
    unsigned a0, unsigned a1, unsigned a2, unsigned a3, unsigned b0, unsigned b1)
{
    asm volatile(
        "mma.sync.aligned.m16n8k16.row.col.f32.f16.f16.f32 "
        "{%0,%1,%2,%3},{%4,%5,%6,%7},{%8,%9},{%0,%1,%2,%3};"
        : "+f"(c[0]), "+f"(c[1]), "+f"(c[2]), "+f"(c[3])
        : "r"(a0), "r"(a1), "r"(a2), "r"(a3), "r"(b0), "r"(b1));
}
__device__ __forceinline__ void ldsm4(unsigned& r0, unsigned& r1, unsigned& r2, unsigned& r3,
                                      uint32_t addr)
{
    asm volatile("ldmatrix.sync.aligned.m8n8.x4.shared.b16 {%0,%1,%2,%3}, [%4];"
        : "=r"(r0), "=r"(r1), "=r"(r2), "=r"(r3) : "r"(addr));
}
__device__ __forceinline__ void cp16(uint32_t dst, const void* src) {
    asm volatile("cp.async.cg.shared.global [%0], [%1], 16;" :: "r"(dst), "l"(src) : "memory");
}
__device__ __forceinline__ void cp_commit() {
    asm volatile("cp.async.commit_group;" ::: "memory");
}
template<int N> __device__ __forceinline__ void cp_wait() {
    asm volatile("cp.async.wait_group %0;" :: "n"(N) : "memory");
}

// ---- gemm1 staging rings: Ah x2 (80B rows), B x4 (80B rows), Af32 x3 (128B rows) ----
constexpr int G1_AH   = 0;                 // 2 * 10240
constexpr int G1_B    = 20480;             // 4 * 10240
constexpr int G1_AF   = 61440;             // 3 * 16384
constexpr int SMEM1g  = 61440 + 49152;     // 110592

// ---- gemm2 (folded, N=16): Araw x3 (16KB), Ah x2 (16KB), Wf (16x1040), bn ----
constexpr int H2_AR   = 0;                 // 3 * 16384 = 49152
constexpr int H2_AH   = 49152;             // 2 * 16384 = 32768
constexpr int H2_BW   = 81920;             // 16 * 1040 = 16640
constexpr int H2_BN   = 98560;             // 2048
constexpr int SMEM2g  = 100608;

// ============================================================================
// convert weights to half (p0W, p1W only)
// ============================================================================
__global__ void convert_w(const float* __restrict__ W0, const float* __restrict__ W1)
{
    int t = blockIdx.x * 256 + threadIdx.x;    // 0..32767
    const float* src; __half* dst; int k;
    if (t < 16384) { src = W0; dst = d_Wh0; k = t; }
    else           { src = W1; dst = d_Wh1; k = t - 16384; }
    const float4 v = reinterpret_cast<const float4*>(src)[k];
    uint2 w; w.x = hpack(v.x, v.y); w.y = hpack(v.z, v.w);
    reinterpret_cast<uint2*>(dst)[k] = w;
}

// ============================================================================
// prep: q / r2 partials -> combine + cconst -> wu rows -> Wfold + cfold
// ============================================================================
__global__ void prep_a(const float* __restrict__ ipW, const float* __restrict__ ipb,
                       const float* __restrict__ opW, const float* __restrict__ rW)
{
    const int b = blockIdx.x, c = threadIdx.x;
    if (b == 8) {
        float s = 0.f;
        for (int k = 0; k < 256; k += 4) {
            float4 v = *reinterpret_cast<const float4*>(&ipW[c * 256 + k]);
            s += v.x + v.y + v.z + v.w;
        }
        d_qv[c] = (s + ipb[c]) * 0.17677669529663687f;
    } else {
        float s = 0.f;
        #pragma unroll 8
        for (int k = b * 32; k < b * 32 + 32; k++)
            s += rW[k] * opW[k * 256 + c];
        d_r2p[b][c] = s;
    }
}

__global__ void prep_b(const float* __restrict__ ipb, const float* __restrict__ opb,
                       const float* __restrict__ rW,  const float* __restrict__ rb)
{
    __shared__ float red[256];
    const int c = threadIdx.x;
    float r2 = 0.f;
    #pragma unroll
    for (int b = 0; b < 8; b++) r2 += d_r2p[b][c];
    d_r2v[c] = r2;
    red[c] = ipb[512 + c] * r2 + rW[c] * opb[c];
    __syncthreads();
    for (int off = 128; off; off >>= 1) {
        if (c < off) red[c] += red[c + off];
        __syncthreads();
    }
    if (c == 0) d_cconst[0] = red[0] + rb[0];
}

__global__ void wu_kernel(const float* __restrict__ ipW)
{
    const int h2 = blockIdx.x, c = threadIdx.x;
    const int h = h2 & 7;
    const float* coeff = (h2 < 8) ? d_qv : d_r2v;
    const int rbase = (h2 < 8) ? 256 : 512;
    float s = 0.f;
    #pragma unroll 8
    for (int d = 0; d < 32; d++)
        s += coeff[h * 32 + d] * ipW[(rbase + h * 32 + d) * 256 + c];
    d_wu[h2 * 256 + c] = s;
}

// Wfold[h2][k] = sum_c wu[h2][c] * Wm[c][k]   (grid 32 x 256)
__global__ void wfold_kernel(const float* __restrict__ mW)
{
    const int t = blockIdx.x * 256 + threadIdx.x;  // 0..8191
    const int k = t >> 4, h2 = t & 15;
    float s = 0.f;
    #pragma unroll 4
    for (int c = 0; c < 256; c++)
        s += d_wu[h2 * 256 + c] * mW[c * 512 + k];
    d_Wfh[h2 * 512 + k] = __float2half(s);
}

// cfold[h2] = sum_c bm[c] * wu[h2][c]
__global__ void cfold_kernel(const float* __restrict__ bm)
{
    const int tid = threadIdx.x;         // 512 threads: warp = h2
    const int h2 = tid >> 5, lane = tid & 31;
    float s = 0.f;
    for (int c = lane; c < 256; c += 32) s += bm[c] * d_wu[h2 * 256 + c];
    #pragma unroll
    for (int off = 16; off; off >>= 1) s += __shfl_xor_sync(0xffffffffu, s, off);
    if (lane == 0) d_cfold[h2] = s;
}

// ============================================================================
// Kernel 2: fused fp32->half + fp16 MMA GEMM  Y = X @ W^T + b  + column stats
// grid (2 nblk, MB, 2 mat), 256 threads, BK=32, 8 chunks, pipelined convert
// ============================================================================
__global__ __launch_bounds__(256, 2)
void gemm1(const float* __restrict__ X0, const float* __restrict__ X1,
           const float* __restrict__ B0, const float* __restrict__ B1)
{
    extern __shared__ char sm[];
    const uint32_t sa = (uint32_t)__cvta_generic_to_shared(sm);

    const int nblk = blockIdx.x;
    const int rb   = blockIdx.y;
    const int mat  = blockIdx.z;
    const float*  __restrict__ Xf = mat ? X1 : X0;
    const __half* __restrict__ Wh = mat ? d_Wh1 : d_Wh0;
    const float*  __restrict__ bias = (mat ? B1 : B0) + nblk * 128;

    const int tid = threadIdx.x, lane = tid & 31, wid = tid >> 5;
    const int wm = wid >> 2, wn = wid & 3;
    const int g = lane >> 2, tq = lane & 3;
    const int row0 = rb * 128;

    const __half* __restrict__ Brow0 = Wh + nblk * 128 * 256;

    const uint32_t aOff = (uint32_t)((wm * 64 + (lane & 15)) * 80 + ((lane >> 4) * 8) * 2);
    const uint32_t bOff = (uint32_t)((wn * 32 + (lane & 7) + ((lane >> 4) << 3)) * 80
                                     + (((lane >> 3) & 1) * 8) * 2);

    auto issue = [&](int s) {
        const uint32_t af = sa + G1_AF + (s % 3) * 16384;
        const uint32_t bb = sa + G1_B  + (s & 3) * 10240;
        const int kt = 32 * s;
        #pragma unroll
        for (int jj = 0; jj < 4; jj++) {
            const int p = tid + 256 * jj;
            const int row = p >> 3, c = p & 7;
            cp16(af + (uint32_t)(row * 128 + ((c * 16) ^ ((row & 7) << 4))),
                 Xf + (row0 + row) * 256 + kt + c * 4);
        }
        #pragma unroll
        for (int jj = 0; jj < 2; jj++) {
            const int p = tid + 256 * jj;
            const int row = p >> 2, c = p & 3;
            cp16(bb + (uint32_t)(row * 80 + c * 16),
                 Brow0 + row * 256 + kt + c * 8);
        }
    };

    auto convert = [&](int s) {
        char* af = sm + G1_AF + (s % 3) * 16384;
        char* ah = sm + G1_AH + (s & 1) * 10240;
        #pragma unroll
        for (int jj = 0; jj < 2; jj++) {
            const int w = tid + 256 * jj;
            const int row = w >> 2, c8 = w & 3;
            const int xo = (row & 7) << 4;
            const float4 f0 = *reinterpret_cast<const float4*>(af + row * 128 + ((c8 * 32) ^ xo));
            const float4 f1 = *reinterpret_cast<const float4*>(af + row * 128 + ((c8 * 32 + 16) ^ xo));
            uint4 hv;
            hv.x = hpack(f0.x, f0.y); hv.y = hpack(f0.z, f0.w);
            hv.z = hpack(f1.x, f1.y); hv.w = hpack(f1.z, f1.w);
            *reinterpret_cast<uint4*>(ah + row * 80 + c8 * 16) = hv;
        }
    };

    float acc[4][4][4];
    #pragma unroll
    for (int mi = 0; mi < 4; mi++)
        #pragma unroll
        for (int ni = 0; ni < 4; ni++)
            #pragma unroll
            for (int e = 0; e < 4; e++) acc[mi][ni][e] = 0.f;

    issue(0); cp_commit();
    issue(1); cp_commit();
    issue(2); cp_commit();
    cp_wait<2>();
    __syncthreads();
    convert(0);

    #pragma unroll 1
    for (int i = 0; i < 8; i++) {
        if (i < 6) cp_wait<1>(); else cp_wait<0>();
        __syncthreads();

        if (i + 1 < 8) convert(i + 1);
        if (i + 3 < 8) { issue(i + 3); cp_commit(); }

        const uint32_t ah = sa + G1_AH + (i & 1) * 10240;
        const uint32_t bb = sa + G1_B  + (i & 3) * 10240;
        #pragma unroll
        for (int kc = 0; kc < 32; kc += 16) {
            unsigned af[4][4], bf[4][2];
            #pragma unroll
            for (int mi = 0; mi < 4; mi++)
                ldsm4(af[mi][0], af[mi][1], af[mi][2], af[mi][3],
                      ah + aOff + mi * 16 * 80 + kc * 2);
            ldsm4(bf[0][0], bf[0][1], bf[1][0], bf[1][1], bb + bOff + kc * 2);
            ldsm4(bf[2][0], bf[2][1], bf[3][0], bf[3][1], bb + bOff + 16 * 80 + kc * 2);
            #pragma unroll
            for (int mi = 0; mi < 4; mi++)
                #pragma unroll
                for (int ni = 0; ni < 4; ni++)
                    mma_f16(acc[mi][ni], af[mi][0], af[mi][1], af[mi][2], af[mi][3],
                            bf[ni][0], bf[ni][1]);
        }
    }

    // ---- epilogue: bias, write Y (half), column stats ----
    float2 bb2[4];
    #pragma unroll
    for (int ni = 0; ni < 4; ni++)
        bb2[ni] = *reinterpret_cast<const float2*>(&bias[wn * 32 + ni * 8 + tq * 2]);
    #pragma unroll
    for (int mi = 0; mi < 4; mi++)
        #pragma unroll
        for (int ni = 0; ni < 4; ni++) {
            acc[mi][ni][0] += bb2[ni].x; acc[mi][ni][1] += bb2[ni].y;
            acc[mi][ni][2] += bb2[ni].x; acc[mi][ni][3] += bb2[ni].y;
        }

    __half* __restrict__ Y = mat ? d_Yh1 : d_Yh0;
    const int colbase = nblk * 128 + wn * 32;
    #pragma unroll
    for (int mi = 0; mi < 4; mi++) {
        const int R0 = row0 + wm * 64 + mi * 16 + g;
        #pragma unroll
        for (int ni = 0; ni < 4; ni++) {
            const int gc = colbase + ni * 8 + tq * 2;
            *reinterpret_cast<unsigned*>(&Y[R0 * 256 + gc])       = hpack(acc[mi][ni][0], acc[mi][ni][1]);
            *reinterpret_cast<unsigned*>(&Y[(R0 + 8) * 256 + gc]) = hpack(acc[mi][ni][2], acc[mi][ni][3]);
        }
    }

    __syncthreads();
    float* ssum = reinterpret_cast<float*>(sm);       // [2][128]
    float* ssq  = ssum + 256;
    #pragma unroll
    for (int ni = 0; ni < 4; ni++) {
        float s0 = 0.f, s1 = 0.f, q0 = 0.f, q1 = 0.f;
        #pragma unroll
        for (int mi = 0; mi < 4; mi++) {
            const float v0 = acc[mi][ni][0], v1 = acc[mi][ni][1];
            const float v2 = acc[mi][ni][2], v3 = acc[mi][ni][3];
            s0 += v0 + v2; s1 += v1 + v3;
            q0 += v0 * v0 + v2 * v2; q1 += v1 * v1 + v3 * v3;
        }
        #pragma unroll
        for (int off = 4; off < 32; off <<= 1) {
            s0 += __shfl_xor_sync(0xffffffffu, s0, off);
            s1 += __shfl_xor_sync(0xffffffffu, s1, off);
            q0 += __shfl_xor_sync(0xffffffffu, q0, off);
            q1 += __shfl_xor_sync(0xffffffffu, q1, off);
        }
        if (lane < 4) {
            const int lcol = wn * 32 + ni * 8 + tq * 2;
            ssum[wm * 128 + lcol] = s0;  ssum[wm * 128 + lcol + 1] = s1;
            ssq [wm * 128 + lcol] = q0;  ssq [wm * 128 + lcol + 1] = q1;
        }
    }
    __syncthreads();
    if (tid < 128) {
        const int gidx = (mat * MB + rb) * 256 + nblk * 128 + tid;
        d_psum  [gidx] = ssum[tid] + ssum[128 + tid];
        d_psumsq[gidx] = ssq [tid] + ssq [128 + tid];
    }
}

// ============================================================================
// Kernels 3/4: deterministic stat reduction -> BN scale/shift
// ============================================================================
__global__ void stats_partial()   // grid 128
{
    const int mat = blockIdx.x >> 6;
    const int sl  = blockIdx.x & 63;
    const int col = threadIdx.x;
    float s = 0.f, q = 0.f;
    const int rb0 = sl * (MB / 64);
    for (int rbi = rb0; rbi < rb0 + (MB / 64); rbi++) {
        s += d_psum  [(mat * MB + rbi) * 256 + col];
        q += d_psumsq[(mat * MB + rbi) * 256 + col];
    }
    d_psum2  [blockIdx.x * 256 + col] = s;
    d_psumsq2[blockIdx.x * 256 + col] = q;
}

__global__ void stats_final(const float* __restrict__ g0, const float* __restrict__ be0,
                            const float* __restrict__ g1, const float* __restrict__ be1)
{
    const int mat = blockIdx.x;
    const int col = threadIdx.x;
    float s = 0.f, q = 0.f;
    #pragma unroll
    for (int sl = 0; sl < 64; sl++) {
        s += d_psum2  [(mat * 64 + sl) * 256 + col];
        q += d_psumsq2[(mat * 64 + sl) * 256 + col];
    }
    const float inv  = 1.0f / (float)NROWS;
    const float mean = s * inv;
    const float var  = fmaxf(q * inv - mean * mean, 0.f);
    const float* gg = mat ? g1 : g0;
    const float* bb = mat ? be1 : be0;
    const float sc = gg[col] * rsqrtf(var + 1e-5f);
    const float sh = bb[col] - mean * sc;
    d_bnscale[mat * 256 + col] = sc;
    d_bnshift[mat * 256 + col] = sh;
    d_bns_h[mat * 256 + col] = __float2half(sc);
    d_bnh_h[mat * 256 + col] = __float2half(sh);
}

// ============================================================================
// Kernel 5 (folded): st = relu_bn(Y) @ Wfold + cfold
// grid (MB), 256 threads (8 warps x 16 rows), BK=64, 8 chunks,
// pipelined BN pass, 2 CTAs/SM, no epilogue reduce
// ============================================================================
__global__ __launch_bounds__(256, 2)
void gemm2()
{
    extern __shared__ char sm[];
    const uint32_t sa = (uint32_t)__cvta_generic_to_shared(sm);
    __half2* bns2 = reinterpret_cast<__half2*>(sm + H2_BN);          // 256 half2
    __half2* bnh2 = reinterpret_cast<__half2*>(sm + H2_BN + 1024);   // 256 half2

    const int tid = threadIdx.x, lane = tid & 31, wid = tid >> 5;
    const int g = lane >> 2, tq = lane & 3;
    const int row0 = blockIdx.x * 128;

    {
        const unsigned* s_src = reinterpret_cast<const unsigned*>(d_bns_h);
        const unsigned* h_src = reinterpret_cast<const unsigned*>(d_bnh_h);
        reinterpret_cast<unsigned*>(bns2)[tid] = s_src[tid];
        reinterpret_cast<unsigned*>(bnh2)[tid] = h_src[tid];
    }

    // ldsm offsets
    const int xr = (lane & 7) << 4;
    const int al16 = (lane >> 4) * 16;
    const uint32_t aRow = (uint32_t)((wid * 16 + (lane & 15)) * 128);
    const uint32_t bOff = (uint32_t)(H2_BW
                        + ((lane & 7) + ((lane >> 4) << 3)) * 1040
                        + (((lane >> 3) & 1) * 8) * 2);

    const int pcb = (tid & 7) * 16;
    const int pch = (tid & 7) * 8;

    auto issue = [&](int s) {
        const uint32_t ar = sa + H2_AR + (s % 3) * 16384;
        const int kt = 64 * s;
        const __half* __restrict__ Ys = (kt < 256) ? d_Yh0 : d_Yh1;
        const int ko = kt & 255;
        #pragma unroll
        for (int j = 0; j < 4; j++) {
            const int row = (tid + 256 * j) >> 3;
            cp16(ar + (uint32_t)(row * 128 + (pcb ^ ((row & 7) << 4))),
                 Ys + (row0 + row) * 256 + ko + pch);
        }
    };

    const __half2 z2 = __float2half2_rn(0.f);

    auto bnpass = [&](int s) {
        char* ar = sm + H2_AR + (s % 3) * 16384;
        char* ah = sm + H2_AH + (s & 1) * 16384;
        const int kt = 64 * s;
        #pragma unroll
        for (int j = 0; j < 4; j++) {
            const int w = tid + 256 * j;
            const int row = w >> 3, c = w & 7;
            const uint32_t off = (uint32_t)(row * 128 + ((c * 16) ^ ((row & 7) << 4)));
            const __half2* rp = reinterpret_cast<const __half2*>(ar + off);
            __half2* wp = reinterpret_cast<__half2*>(ah + off);
            const int si = (kt >> 1) + c * 4;
            const __half2 s0 = bns2[si], s1 = bns2[si + 1], s2 = bns2[si + 2], s3 = bns2[si + 3];
            const __half2 h0 = bnh2[si], h1 = bnh2[si + 1], h2 = bnh2[si + 2], h3 = bnh2[si + 3];
            __half2 v0 = rp[0], v1 = rp[1], v2 = rp[2], v3 = rp[3];
            v0 = __hmax2(__hfma2(v0, s0, h0), z2);
            v1 = __hmax2(__hfma2(v1, s1, h1), z2);
            v2 = __hmax2(__hfma2(v2, s2, h2), z2);
            v3 = __hmax2(__hfma2(v3, s3, h3), z2);
            wp[0] = v0; wp[1] = v1; wp[2] = v2; wp[3] = v3;
        }
    };

    float acc[2][4];
    #pragma unroll
    for (int ni = 0; ni < 2; ni++)
        #pragma unroll
        for (int e = 0; e < 4; e++) acc[ni][e] = 0.f;

    // stage Wfold (16 rows x 1024B -> stride 1040) with chunk-0's cp group
    issue(0);
    {
        #pragma unroll
        for (int j = 0; j < 4; j++) {
            const int p = tid + 256 * j;       // 0..1023
            const int row = p >> 6, c = p & 63;
            cp16(sa + H2_BW + (uint32_t)(row * 1040 + c * 16),
                 d_Wfh + row * 512 + c * 8);
        }
    }
    cp_commit();
    issue(1); cp_commit();
    issue(2); cp_commit();
    cp_wait<2>();
    __syncthreads();
    bnpass(0);

    #pragma unroll 1
    for (int i = 0; i < 8; i++) {
        if (i < 6) cp_wait<1>(); else cp_wait<0>();
        __syncthreads();

        if (i + 1 < 8) bnpass(i + 1);
        if (i + 3 < 8) { issue(i + 3); cp_commit(); }

        const uint32_t ah = sa + H2_AH + (i & 1) * 16384;
        #pragma unroll
        for (int ks = 0; ks < 4; ks++) {
            unsigned af[4], bf[4];
            ldsm4(af[0], af[1], af[2], af[3], ah + aRow + ((ks * 32 + al16) ^ xr));
            ldsm4(bf[0], bf[1], bf[2], bf[3], bOff + sa + (uint32_t)((i * 64 + ks * 16) * 2));
            mma_f16(acc[0], af[0], af[1], af[2], af[3], bf[0], bf[1]);
            mma_f16(acc[1], af[0], af[1], af[2], af[3], bf[2], bf[3]);
        }
    }

    // ---- epilogue: + cfold, write d_st directly ----
    const int r0 = row0 + wid * 16 + g;
    #pragma unroll
    for (int ni = 0; ni < 2; ni++) {
        const float2 cf = *reinterpret_cast<const float2*>(&d_cfold[ni * 8 + tq * 2]);
        float2 lo = make_float2(acc[ni][0] + cf.x, acc[ni][1] + cf.y);
        float2 hi = make_float2(acc[ni][2] + cf.x, acc[ni][3] + cf.y);
        *reinterpret_cast<float2*>(&d_st[r0 * 16 + ni * 8 + tq * 2])       = lo;
        *reinterpret_cast<float2*>(&d_st[(r0 + 8) * 16 + ni * 8 + tq * 2]) = hi;
    }
}

// ============================================================================
// Kernel 6: per-group softmax-weighted mean + tanh readout
// ============================================================================
__global__ void groups_kernel(float* __restrict__ out)
{
    __shared__ float sb[NPGC * 16];
    __shared__ float hv[8];
    const int g = blockIdx.x;
    const int tid = threadIdx.x;
    const float* __restrict__ b0 = &d_st[g * (NPGC * 16)];
    for (int i = tid; i < NPGC * 16; i += 256) sb[i] = b0[i];
    __syncthreads();

    const int h    = tid >> 5;
    const int lane = tid & 31;

    float mx = -1e30f;
    for (int r = lane; r < NPGC; r += 32) mx = fmaxf(mx, sb[r * 16 + h]);
    #pragma unroll
    for (int off = 16; off; off >>= 1) mx = fmaxf(mx, __shfl_xor_sync(0xffffffffu, mx, off));

    float num = 0.f, den = 0.f;
    for (int r = lane; r < NPGC; r += 32) {
        const float e = expf(sb[r * 16 + h] - mx);
        num = fmaf(e, sb[r * 16 + 8 + h], num);
        den += e;
    }
    #pragma unroll
    for (int off = 16; off; off >>= 1) {
        num += __shfl_xor_sync(0xffffffffu, num, off);
        den += __shfl_xor_sync(0xffffffffu, den, off);
    }
    if (lane == 0) hv[h] = num / den;
    __syncthreads();

    if (tid == 0) {
        float s = d_cconst[0];
        #pragma unroll
        for (int i = 0; i < 8; i++) s += hv[i];
        out[g] = tanhf(s);
    }
}

// ============================================================================
extern "C" void kernel_launch(void* const* d_in, const int* in_sizes, int n_in,
                              void* d_out, int out_size)
{
    const float* x0   = (const float*)d_in[0];
    const float* x1   = (const float*)d_in[1];
    const float* p0W  = (const float*)d_in[3];
    const float* p0b  = (const float*)d_in[4];
    const float* p0g  = (const float*)d_in[5];
    const float* p0be = (const float*)d_in[6];
    const float* p1W  = (const float*)d_in[7];
    const float* p1b  = (const float*)d_in[8];
    const float* p1g  = (const float*)d_in[9];
    const float* p1be = (const float*)d_in[10];
    const float* mW   = (const float*)d_in[11];
    const float* mb   = (const float*)d_in[12];
    const float* ipW  = (const float*)d_in[13];
    const float* ipb  = (const float*)d_in[14];
    const float* opW  = (const float*)d_in[15];
    const float* opb  = (const float*)d_in[16];
    const float* rW   = (const float*)d_in[17];
    const float* rb   = (const float*)d_in[18];
    float* out = (float*)d_out;

    cudaFuncSetAttribute(gemm1, cudaFuncAttributeMaxDynamicSharedMemorySize, SMEM1g);
    cudaFuncSetAttribute(gemm2, cudaFuncAttributeMaxDynamicSharedMemorySize, SMEM2g);

    prep_a<<<9, 256>>>(ipW, ipb, opW, rW);
    prep_b<<<1, 256>>>(ipb, opb, rW, rb);
    wu_kernel<<<16, 256>>>(ipW);
    wfold_kernel<<<32, 256>>>(mW);
    cfold_kernel<<<1, 512>>>(mb);
    convert_w<<<128, 256>>>(p0W, p1W);
    gemm1<<<dim3(2, MB, 2), 256, SMEM1g>>>(x0, x1, p0b, p1b);
    stats_partial<<<128, 256>>>();
    stats_final<<<2, 256>>>(p0g, p0be, p1g, p1be);
    gemm2<<<MB, 256, SMEM2g>>>();
    groups_kernel<<<NG, 256>>>(out);
}

// round 17
// speedup vs baseline: 1.8106x; 1.0819x over previous
#include <cuda_runtime.h>
#include <cuda_fp16.h>
#include <cstdint>
#include <math.h>

#define NROWS 204800
#define NG    2048
#define NPGC  100
#define MB    1600            // NROWS / 128

// ---- scratch (device globals; allocation forbidden) ----
__device__ __half d_Yh0[NROWS * 256];
__device__ __half d_Yh1[NROWS * 256];
__device__ __half d_Wh0[256 * 256];
__device__ __half d_Wh1[256 * 256];
__device__ float d_psum  [2 * MB * 256];
__device__ float d_psumsq[2 * MB * 256];
__device__ float d_psum2  [128 * 256];
__device__ float d_psumsq2[128 * 256];
__device__ float d_bnscale[512];
__device__ float d_bnshift[512];
__device__ __half d_bns_h[512];
__device__ __half d_bnh_h[512];
__device__ float d_qv[256];
__device__ float d_r2p[8][256];
__device__ float d_r2v[256];
__device__ float d_wu[16 * 256];        // rows 0..7: ws_h ; rows 8..15: u_h
__device__ __align__(16) __half d_Wfh[16 * 512];   // Wfold: [h2][k]
__device__ float d_cfold[16];
__device__ float d_cconst[1];
__device__ float d_st[NROWS * 16];      // per row: [scores(8) | t(8)]

// ---- helpers ----
__device__ __forceinline__ unsigned hpack(float a, float b) {
    __half2 h = __floats2half2_rn(a, b);
    return *reinterpret_cast<unsigned*>(&h);
}
__device__ __forceinline__ void mma_f16(float c[4],
    unsigned a0, unsigned a1, unsigned a2, unsigned a3, unsigned b0, unsigned b1)
{
    asm volatile(
        "mma.sync.aligned.m16n8k16.row.col.f32.f16.f16.f32 "
        "{%0,%1,%2,%3},{%4,%5,%6,%7},{%8,%9},{%0,%1,%2,%3};"
        : "+f"(c[0]), "+f"(c[1]), "+f"(c[2]), "+f"(c[3])
        : "r"(a0), "r"(a1), "r"(a2), "r"(a3), "r"(b0), "r"(b1));
}
__device__ __forceinline__ void ldsm4(unsigned& r0, unsigned& r1, unsigned& r2, unsigned& r3,
                                      uint32_t addr)
{
    asm volatile("ldmatrix.sync.aligned.m8n8.x4.shared.b16 {%0,%1,%2,%3}, [%4];"
        : "=r"(r0), "=r"(r1), "=r"(r2), "=r"(r3) : "r"(addr));
}
__device__ __forceinline__ void cp16(uint32_t dst, const void* src) {
    asm volatile("cp.async.cg.shared.global [%0], [%1], 16;" :: "r"(dst), "l"(src) : "memory");
}
__device__ __forceinline__ void cp_commit() {
    asm volatile("cp.async.commit_group;" ::: "memory");
}
template<int N> __device__ __forceinline__ void cp_wait() {
    asm volatile("cp.async.wait_group %0;" :: "n"(N) : "memory");
}

// ---- gemm1 staging rings: Ah x2 (80B rows), B x4 (80B rows), Af32 x3 (128B rows) ----
constexpr int G1_AH   = 0;                 // 2 * 10240
constexpr int G1_B    = 20480;             // 4 * 10240
constexpr int G1_AF   = 61440;             // 3 * 16384
constexpr int SMEM1g  = 61440 + 49152;     // 110592

// ---- gemm2 (folded, N=16): Araw x3 (16KB), Ah x2 (16KB), Wf (16x1040), bn ----
constexpr int H2_AR   = 0;                 // 3 * 16384 = 49152
constexpr int H2_AH   = 49152;             // 2 * 16384 = 32768
constexpr int H2_BW   = 81920;             // 16 * 1040 = 16640
constexpr int H2_BN   = 98560;             // 2048
constexpr int SMEM2g  = 100608;

// ============================================================================
// convert weights to half (p0W, p1W only)
// ============================================================================
__global__ void convert_w(const float* __restrict__ W0, const float* __restrict__ W1)
{
    int t = blockIdx.x * 256 + threadIdx.x;    // 0..32767
    const float* src; __half* dst; int k;
    if (t < 16384) { src = W0; dst = d_Wh0; k = t; }
    else           { src = W1; dst = d_Wh1; k = t - 16384; }
    const float4 v = reinterpret_cast<const float4*>(src)[k];
    uint2 w; w.x = hpack(v.x, v.y); w.y = hpack(v.z, v.w);
    reinterpret_cast<uint2*>(dst)[k] = w;
}

// ============================================================================
// prep: q / r2 partials -> combine + cconst -> wu rows -> Wfold + cfold
// ============================================================================
__global__ void prep_a(const float* __restrict__ ipW, const float* __restrict__ ipb,
                       const float* __restrict__ opW, const float* __restrict__ rW)
{
    const int b = blockIdx.x, c = threadIdx.x;
    if (b == 8) {
        float s = 0.f;
        for (int k = 0; k < 256; k += 4) {
            float4 v = *reinterpret_cast<const float4*>(&ipW[c * 256 + k]);
            s += v.x + v.y + v.z + v.w;
        }
        d_qv[c] = (s + ipb[c]) * 0.17677669529663687f;
    } else {
        float s = 0.f;
        #pragma unroll 8
        for (int k = b * 32; k < b * 32 + 32; k++)
            s += rW[k] * opW[k * 256 + c];
        d_r2p[b][c] = s;
    }
}

__global__ void prep_b(const float* __restrict__ ipb, const float* __restrict__ opb,
                       const float* __restrict__ rW,  const float* __restrict__ rb)
{
    __shared__ float red[256];
    const int c = threadIdx.x;
    float r2 = 0.f;
    #pragma unroll
    for (int b = 0; b < 8; b++) r2 += d_r2p[b][c];
    d_r2v[c] = r2;
    red[c] = ipb[512 + c] * r2 + rW[c] * opb[c];
    __syncthreads();
    for (int off = 128; off; off >>= 1) {
        if (c < off) red[c] += red[c + off];
        __syncthreads();
    }
    if (c == 0) d_cconst[0] = red[0] + rb[0];
}

__global__ void wu_kernel(const float* __restrict__ ipW)
{
    const int h2 = blockIdx.x, c = threadIdx.x;
    const int h = h2 & 7;
    const float* coeff = (h2 < 8) ? d_qv : d_r2v;
    const int rbase = (h2 < 8) ? 256 : 512;
    float s = 0.f;
    #pragma unroll 8
    for (int d = 0; d < 32; d++)
        s += coeff[h * 32 + d] * ipW[(rbase + h * 32 + d) * 256 + c];
    d_wu[h2 * 256 + c] = s;
}

// Wfold[h2][k] = sum_c wu[h2][c] * Wm[c][k]
// grid 16: block b owns k in [b*32, b*32+32); warp = c-slice of 32.
__global__ void wfold_kernel(const float* __restrict__ mW)
{
    __shared__ float wuS[16 * 256];          // 16 KB
    __shared__ float part[8][32][16];        // 16 KB
    const int b = blockIdx.x;
    const int tid = threadIdx.x;
    const int kloc = tid & 31, cs = tid >> 5;
    const int k = b * 32 + kloc;

    for (int i = tid; i < 4096; i += 256) wuS[i] = d_wu[i];
    __syncthreads();

    float s[16];
    #pragma unroll
    for (int h2 = 0; h2 < 16; h2++) s[h2] = 0.f;
    #pragma unroll 4
    for (int c = cs * 32; c < cs * 32 + 32; c++) {
        const float m = mW[c * 512 + k];     // coalesced over lanes
        #pragma unroll
        for (int h2 = 0; h2 < 16; h2++) s[h2] += wuS[h2 * 256 + c] * m;
    }
    #pragma unroll
    for (int h2 = 0; h2 < 16; h2++) part[cs][kloc][h2] = s[h2];
    __syncthreads();

    for (int p = tid; p < 512; p += 256) {
        const int kk = p >> 4, h2 = p & 15;
        float acc = 0.f;
        #pragma unroll
        for (int q = 0; q < 8; q++) acc += part[q][kk][h2];
        d_Wfh[h2 * 512 + b * 32 + kk] = __float2half(acc);
    }
}

// cfold[h2] = sum_c bm[c] * wu[h2][c]
__global__ void cfold_kernel(const float* __restrict__ bm)
{
    const int tid = threadIdx.x;         // 512 threads: warp = h2
    const int h2 = tid >> 5, lane = tid & 31;
    float s = 0.f;
    for (int c = lane; c < 256; c += 32) s += bm[c] * d_wu[h2 * 256 + c];
    #pragma unroll
    for (int off = 16; off; off >>= 1) s += __shfl_xor_sync(0xffffffffu, s, off);
    if (lane == 0) d_cfold[h2] = s;
}

// ============================================================================
// Kernel 2: fused fp32->half + fp16 MMA GEMM  Y = X @ W^T + b  + column stats
// grid (2 nblk, MB, 2 mat), 256 threads, BK=32, 8 chunks, pipelined convert
// ============================================================================
__global__ __launch_bounds__(256, 2)
void gemm1(const float* __restrict__ X0, const float* __restrict__ X1,
           const float* __restrict__ B0, const float* __restrict__ B1)
{
    extern __shared__ char sm[];
    const uint32_t sa = (uint32_t)__cvta_generic_to_shared(sm);

    const int nblk = blockIdx.x;
    const int rb   = blockIdx.y;
    const int mat  = blockIdx.z;
    const float*  __restrict__ Xf = mat ? X1 : X0;
    const __half* __restrict__ Wh = mat ? d_Wh1 : d_Wh0;
    const float*  __restrict__ bias = (mat ? B1 : B0) + nblk * 128;

    const int tid = threadIdx.x, lane = tid & 31, wid = tid >> 5;
    const int wm = wid >> 2, wn = wid & 3;
    const int g = lane >> 2, tq = lane & 3;
    const int row0 = rb * 128;

    const __half* __restrict__ Brow0 = Wh + nblk * 128 * 256;

    const uint32_t aOff = (uint32_t)((wm * 64 + (lane & 15)) * 80 + ((lane >> 4) * 8) * 2);
    const uint32_t bOff = (uint32_t)((wn * 32 + (lane & 7) + ((lane >> 4) << 3)) * 80
                                     + (((lane >> 3) & 1) * 8) * 2);

    auto issue = [&](int s) {
        const uint32_t af = sa + G1_AF + (s % 3) * 16384;
        const uint32_t bb = sa + G1_B  + (s & 3) * 10240;
        const int kt = 32 * s;
        #pragma unroll
        for (int jj = 0; jj < 4; jj++) {
            const int p = tid + 256 * jj;
            const int row = p >> 3, c = p & 7;
            cp16(af + (uint32_t)(row * 128 + ((c * 16) ^ ((row & 7) << 4))),
                 Xf + (row0 + row) * 256 + kt + c * 4);
        }
        #pragma unroll
        for (int jj = 0; jj < 2; jj++) {
            const int p = tid + 256 * jj;
            const int row = p >> 2, c = p & 3;
            cp16(bb + (uint32_t)(row * 80 + c * 16),
                 Brow0 + row * 256 + kt + c * 8);
        }
    };

    auto convert = [&](int s) {
        char* af = sm + G1_AF + (s % 3) * 16384;
        char* ah = sm + G1_AH + (s & 1) * 10240;
        #pragma unroll
        for (int jj = 0; jj < 2; jj++) {
            const int w = tid + 256 * jj;
            const int row = w >> 2, c8 = w & 3;
            const int xo = (row & 7) << 4;
            const float4 f0 = *reinterpret_cast<const float4*>(af + row * 128 + ((c8 * 32) ^ xo));
            const float4 f1 = *reinterpret_cast<const float4*>(af + row * 128 + ((c8 * 32 + 16) ^ xo));
            uint4 hv;
            hv.x = hpack(f0.x, f0.y); hv.y = hpack(f0.z, f0.w);
            hv.z = hpack(f1.x, f1.y); hv.w = hpack(f1.z, f1.w);
            *reinterpret_cast<uint4*>(ah + row * 80 + c8 * 16) = hv;
        }
    };

    float acc[4][4][4];
    #pragma unroll
    for (int mi = 0; mi < 4; mi++)
        #pragma unroll
        for (int ni = 0; ni < 4; ni++)
            #pragma unroll
            for (int e = 0; e < 4; e++) acc[mi][ni][e] = 0.f;

    issue(0); cp_commit();
    issue(1); cp_commit();
    issue(2); cp_commit();
    cp_wait<2>();
    __syncthreads();
    convert(0);

    #pragma unroll 1
    for (int i = 0; i < 8; i++) {
        if (i < 6) cp_wait<1>(); else cp_wait<0>();
        __syncthreads();

        if (i + 1 < 8) convert(i + 1);
        if (i + 3 < 8) { issue(i + 3); cp_commit(); }

        const uint32_t ah = sa + G1_AH + (i & 1) * 10240;
        const uint32_t bb = sa + G1_B  + (i & 3) * 10240;
        #pragma unroll
        for (int kc = 0; kc < 32; kc += 16) {
            unsigned af[4][4], bf[4][2];
            #pragma unroll
            for (int mi = 0; mi < 4; mi++)
                ldsm4(af[mi][0], af[mi][1], af[mi][2], af[mi][3],
                      ah + aOff + mi * 16 * 80 + kc * 2);
            ldsm4(bf[0][0], bf[0][1], bf[1][0], bf[1][1], bb + bOff + kc * 2);
            ldsm4(bf[2][0], bf[2][1], bf[3][0], bf[3][1], bb + bOff + 16 * 80 + kc * 2);
            #pragma unroll
            for (int mi = 0; mi < 4; mi++)
                #pragma unroll
                for (int ni = 0; ni < 4; ni++)
                    mma_f16(acc[mi][ni], af[mi][0], af[mi][1], af[mi][2], af[mi][3],
                            bf[ni][0], bf[ni][1]);
        }
    }

    // ---- epilogue: bias, write Y (half), column stats ----
    float2 bb2[4];
    #pragma unroll
    for (int ni = 0; ni < 4; ni++)
        bb2[ni] = *reinterpret_cast<const float2*>(&bias[wn * 32 + ni * 8 + tq * 2]);
    #pragma unroll
    for (int mi = 0; mi < 4; mi++)
        #pragma unroll
        for (int ni = 0; ni < 4; ni++) {
            acc[mi][ni][0] += bb2[ni].x; acc[mi][ni][1] += bb2[ni].y;
            acc[mi][ni][2] += bb2[ni].x; acc[mi][ni][3] += bb2[ni].y;
        }

    __half* __restrict__ Y = mat ? d_Yh1 : d_Yh0;
    const int colbase = nblk * 128 + wn * 32;
    #pragma unroll
    for (int mi = 0; mi < 4; mi++) {
        const int R0 = row0 + wm * 64 + mi * 16 + g;
        #pragma unroll
        for (int ni = 0; ni < 4; ni++) {
            const int gc = colbase + ni * 8 + tq * 2;
            *reinterpret_cast<unsigned*>(&Y[R0 * 256 + gc])       = hpack(acc[mi][ni][0], acc[mi][ni][1]);
            *reinterpret_cast<unsigned*>(&Y[(R0 + 8) * 256 + gc]) = hpack(acc[mi][ni][2], acc[mi][ni][3]);
        }
    }

    __syncthreads();
    float* ssum = reinterpret_cast<float*>(sm);       // [2][128]
    float* ssq  = ssum + 256;
    #pragma unroll
    for (int ni = 0; ni < 4; ni++) {
        float s0 = 0.f, s1 = 0.f, q0 = 0.f, q1 = 0.f;
        #pragma unroll
        for (int mi = 0; mi < 4; mi++) {
            const float v0 = acc[mi][ni][0], v1 = acc[mi][ni][1];
            const float v2 = acc[mi][ni][2], v3 = acc[mi][ni][3];
            s0 += v0 + v2; s1 += v1 + v3;
            q0 += v0 * v0 + v2 * v2; q1 += v1 * v1 + v3 * v3;
        }
        #pragma unroll
        for (int off = 4; off < 32; off <<= 1) {
            s0 += __shfl_xor_sync(0xffffffffu, s0, off);
            s1 += __shfl_xor_sync(0xffffffffu, s1, off);
            q0 += __shfl_xor_sync(0xffffffffu, q0, off);
            q1 += __shfl_xor_sync(0xffffffffu, q1, off);
        }
        if (lane < 4) {
            const int lcol = wn * 32 + ni * 8 + tq * 2;
            ssum[wm * 128 + lcol] = s0;  ssum[wm * 128 + lcol + 1] = s1;
            ssq [wm * 128 + lcol] = q0;  ssq [wm * 128 + lcol + 1] = q1;
        }
    }
    __syncthreads();
    if (tid < 128) {
        const int gidx = (mat * MB + rb) * 256 + nblk * 128 + tid;
        d_psum  [gidx] = ssum[tid] + ssum[128 + tid];
        d_psumsq[gidx] = ssq [tid] + ssq [128 + tid];
    }
}

// ============================================================================
// Kernels 3/4: deterministic stat reduction -> BN scale/shift
// ============================================================================
__global__ void stats_partial()   // grid 128
{
    const int mat = blockIdx.x >> 6;
    const int sl  = blockIdx.x & 63;
    const int col = threadIdx.x;
    float s = 0.f, q = 0.f;
    const int rb0 = sl * (MB / 64);
    for (int rbi = rb0; rbi < rb0 + (MB / 64); rbi++) {
        s += d_psum  [(mat * MB + rbi) * 256 + col];
        q += d_psumsq[(mat * MB + rbi) * 256 + col];
    }
    d_psum2  [blockIdx.x * 256 + col] = s;
    d_psumsq2[blockIdx.x * 256 + col] = q;
}

__global__ void stats_final(const float* __restrict__ g0, const float* __restrict__ be0,
                            const float* __restrict__ g1, const float* __restrict__ be1)
{
    const int mat = blockIdx.x;
    const int col = threadIdx.x;
    float s = 0.f, q = 0.f;
    #pragma unroll
    for (int sl = 0; sl < 64; sl++) {
        s += d_psum2  [(mat * 64 + sl) * 256 + col];
        q += d_psumsq2[(mat * 64 + sl) * 256 + col];
    }
    const float inv  = 1.0f / (float)NROWS;
    const float mean = s * inv;
    const float var  = fmaxf(q * inv - mean * mean, 0.f);
    const float* gg = mat ? g1 : g0;
    const float* bb = mat ? be1 : be0;
    const float sc = gg[col] * rsqrtf(var + 1e-5f);
    const float sh = bb[col] - mean * sc;
    d_bnscale[mat * 256 + col] = sc;
    d_bnshift[mat * 256 + col] = sh;
    d_bns_h[mat * 256 + col] = __float2half(sc);
    d_bnh_h[mat * 256 + col] = __float2half(sh);
}

// ============================================================================
// Kernel 5 (folded): st = relu_bn(Y) @ Wfold + cfold
// grid (MB), 256 threads (8 warps x 16 rows), BK=64, 8 chunks,
// pipelined BN pass, 2 CTAs/SM, no epilogue reduce
// ============================================================================
__global__ __launch_bounds__(256, 2)
void gemm2()
{
    extern __shared__ char sm[];
    const uint32_t sa = (uint32_t)__cvta_generic_to_shared(sm);
    __half2* bns2 = reinterpret_cast<__half2*>(sm + H2_BN);          // 256 half2
    __half2* bnh2 = reinterpret_cast<__half2*>(sm + H2_BN + 1024);   // 256 half2

    const int tid = threadIdx.x, lane = tid & 31, wid = tid >> 5;
    const int g = lane >> 2, tq = lane & 3;
    const int row0 = blockIdx.x * 128;

    {
        const unsigned* s_src = reinterpret_cast<const unsigned*>(d_bns_h);
        const unsigned* h_src = reinterpret_cast<const unsigned*>(d_bnh_h);
        reinterpret_cast<unsigned*>(bns2)[tid] = s_src[tid];
        reinterpret_cast<unsigned*>(bnh2)[tid] = h_src[tid];
    }

    const int xr = (lane & 7) << 4;
    const int al16 = (lane >> 4) * 16;
    const uint32_t aRow = (uint32_t)((wid * 16 + (lane & 15)) * 128);
    const uint32_t bOff = (uint32_t)(H2_BW
                        + ((lane & 7) + ((lane >> 4) << 3)) * 1040
                        + (((lane >> 3) & 1) * 8) * 2);

    const int pcb = (tid & 7) * 16;
    const int pch = (tid & 7) * 8;

    auto issue = [&](int s) {
        const uint32_t ar = sa + H2_AR + (s % 3) * 16384;
        const int kt = 64 * s;
        const __half* __restrict__ Ys = (kt < 256) ? d_Yh0 : d_Yh1;
        const int ko = kt & 255;
        #pragma unroll
        for (int j = 0; j < 4; j++) {
            const int row = (tid + 256 * j) >> 3;
            cp16(ar + (uint32_t)(row * 128 + (pcb ^ ((row & 7) << 4))),
                 Ys + (row0 + row) * 256 + ko + pch);
        }
    };

    const __half2 z2 = __float2half2_rn(0.f);

    auto bnpass = [&](int s) {
        char* ar = sm + H2_AR + (s % 3) * 16384;
        char* ah = sm + H2_AH + (s & 1) * 16384;
        const int kt = 64 * s;
        #pragma unroll
        for (int j = 0; j < 4; j++) {
            const int w = tid + 256 * j;
            const int row = w >> 3, c = w & 7;
            const uint32_t off = (uint32_t)(row * 128 + ((c * 16) ^ ((row & 7) << 4)));
            const __half2* rp = reinterpret_cast<const __half2*>(ar + off);
            __half2* wp = reinterpret_cast<__half2*>(ah + off);
            const int si = (kt >> 1) + c * 4;
            const __half2 s0 = bns2[si], s1 = bns2[si + 1], s2 = bns2[si + 2], s3 = bns2[si + 3];
            const __half2 h0 = bnh2[si], h1 = bnh2[si + 1], h2 = bnh2[si + 2], h3 = bnh2[si + 3];
            __half2 v0 = rp[0], v1 = rp[1], v2 = rp[2], v3 = rp[3];
            v0 = __hmax2(__hfma2(v0, s0, h0), z2);
            v1 = __hmax2(__hfma2(v1, s1, h1), z2);
            v2 = __hmax2(__hfma2(v2, s2, h2), z2);
            v3 = __hmax2(__hfma2(v3, s3, h3), z2);
            wp[0] = v0; wp[1] = v1; wp[2] = v2; wp[3] = v3;
        }
    };

    float acc[2][4];
    #pragma unroll
    for (int ni = 0; ni < 2; ni++)
        #pragma unroll
        for (int e = 0; e < 4; e++) acc[ni][e] = 0.f;

    issue(0);
    {
        #pragma unroll
        for (int j = 0; j < 4; j++) {
            const int p = tid + 256 * j;       // 0..1023
            const int row = p >> 6, c = p & 63;
            cp16(sa + H2_BW + (uint32_t)(row * 1040 + c * 16),
                 d_Wfh + row * 512 + c * 8);
        }
    }
    cp_commit();
    issue(1); cp_commit();
    issue(2); cp_commit();
    cp_wait<2>();
    __syncthreads();
    bnpass(0);

    #pragma unroll 1
    for (int i = 0; i < 8; i++) {
        if (i < 6) cp_wait<1>(); else cp_wait<0>();
        __syncthreads();

        if (i + 1 < 8) bnpass(i + 1);
        if (i + 3 < 8) { issue(i + 3); cp_commit(); }

        const uint32_t ah = sa + H2_AH + (i & 1) * 16384;
        #pragma unroll
        for (int ks = 0; ks < 4; ks++) {
            unsigned af[4], bf[4];
            ldsm4(af[0], af[1], af[2], af[3], ah + aRow + ((ks * 32 + al16) ^ xr));
            ldsm4(bf[0], bf[1], bf[2], bf[3], bOff + sa + (uint32_t)((i * 64 + ks * 16) * 2));
            mma_f16(acc[0], af[0], af[1], af[2], af[3], bf[0], bf[1]);
            mma_f16(acc[1], af[0], af[1], af[2], af[3], bf[2], bf[3]);
        }
    }

    // ---- epilogue: + cfold, write d_st directly ----
    const int r0 = row0 + wid * 16 + g;
    #pragma unroll
    for (int ni = 0; ni < 2; ni++) {
        const float2 cf = *reinterpret_cast<const float2*>(&d_cfold[ni * 8 + tq * 2]);
        float2 lo = make_float2(acc[ni][0] + cf.x, acc[ni][1] + cf.y);
        float2 hi = make_float2(acc[ni][2] + cf.x, acc[ni][3] + cf.y);
        *reinterpret_cast<float2*>(&d_st[r0 * 16 + ni * 8 + tq * 2])       = lo;
        *reinterpret_cast<float2*>(&d_st[(r0 + 8) * 16 + ni * 8 + tq * 2]) = hi;
    }
}

// ============================================================================
// Kernel 6: per-group softmax-weighted mean + tanh readout
// ============================================================================
__global__ void groups_kernel(float* __restrict__ out)
{
    __shared__ float sb[NPGC * 16];
    __shared__ float hv[8];
    const int g = blockIdx.x;
    const int tid = threadIdx.x;
    const float* __restrict__ b0 = &d_st[g * (NPGC * 16)];
    for (int i = tid; i < NPGC * 16; i += 256) sb[i] = b0[i];
    __syncthreads();

    const int h    = tid >> 5;
    const int lane = tid & 31;

    float mx = -1e30f;
    for (int r = lane; r < NPGC; r += 32) mx = fmaxf(mx, sb[r * 16 + h]);
    #pragma unroll
    for (int off = 16; off; off >>= 1) mx = fmaxf(mx, __shfl_xor_sync(0xffffffffu, mx, off));

    float num = 0.f, den = 0.f;
    for (int r = lane; r < NPGC; r += 32) {
        const float e = expf(sb[r * 16 + h] - mx);
        num = fmaf(e, sb[r * 16 + 8 + h], num);
        den += e;
    }
    #pragma unroll
    for (int off = 16; off; off >>= 1) {
        num += __shfl_xor_sync(0xffffffffu, num, off);
        den += __shfl_xor_sync(0xffffffffu, den, off);
    }
    if (lane == 0) hv[h] = num / den;
    __syncthreads();

    if (tid == 0) {
        float s = d_cconst[0];
        #pragma unroll
        for (int i = 0; i < 8; i++) s += hv[i];
        out[g] = tanhf(s);
    }
}

// ============================================================================
extern "C" void kernel_launch(void* const* d_in, const int* in_sizes, int n_in,
                              void* d_out, int out_size)
{
    const float* x0   = (const float*)d_in[0];
    const float* x1   = (const float*)d_in[1];
    const float* p0W  = (const float*)d_in[3];
    const float* p0b  = (const float*)d_in[4];
    const float* p0g  = (const float*)d_in[5];
    const float* p0be = (const float*)d_in[6];
    const float* p1W  = (const float*)d_in[7];
    const float* p1b  = (const float*)d_in[8];
    const float* p1g  = (const float*)d_in[9];
    const float* p1be = (const float*)d_in[10];
    const float* mW   = (const float*)d_in[11];
    const float* mb   = (const float*)d_in[12];
    const float* ipW  = (const float*)d_in[13];
    const float* ipb  = (const float*)d_in[14];
    const float* opW  = (const float*)d_in[15];
    const float* opb  = (const float*)d_in[16];
    const float* rW   = (const float*)d_in[17];
    const float* rb   = (const float*)d_in[18];
    float* out = (float*)d_out;

    cudaFuncSetAttribute(gemm1, cudaFuncAttributeMaxDynamicSharedMemorySize, SMEM1g);
    cudaFuncSetAttribute(gemm2, cudaFuncAttributeMaxDynamicSharedMemorySize, SMEM2g);

    prep_a<<<9, 256>>>(ipW, ipb, opW, rW);
    prep_b<<<1, 256>>>(ipb, opb, rW, rb);
    wu_kernel<<<16, 256>>>(ipW);
    wfold_kernel<<<16, 256>>>(mW);
    cfold_kernel<<<1, 512>>>(mb);
    convert_w<<<128, 256>>>(p0W, p1W);
    gemm1<<<dim3(2, MB, 2), 256, SMEM1g>>>(x0, x1, p0b, p1b);
    stats_partial<<<128, 256>>>();
    stats_final<<<2, 256>>>(p0g, p0be, p1g, p1be);
    gemm2<<<MB, 256, SMEM2g>>>();
    groups_kernel<<<NG, 256>>>(out);
}